// round 2
// baseline (speedup 1.0000x reference)
#include <cuda_runtime.h>
#include <math.h>

// ---------------------------------------------------------------------------
// Connectivity3D: fused PointNet (6->64->128->256 + BN + maxpool) followed by
// the algebraically-collapsed GCN/edge-MLP head (everything per-object).
// ---------------------------------------------------------------------------

#define PARTS 8192
#define PPTS  512
#define NOBJ  512
#define TILE  16
#define NTILES (PPTS / TILE)   // 32

// Scratch (device globals: no allocations allowed)
__device__ float g_feat[PARTS * 256];     // per-part 256-dim features (8 MB)
__device__ float g_fmean[NOBJ * 256];     // per-object mean feature
__device__ float g_bufA[NOBJ * 256];
__device__ float g_bufB[NOBJ * 256];
__device__ float g_wc1s[256 * 256];       // Wc1[:256] + Wc1[256:]
__device__ float g_s[NOBJ];               // per-object edge score

// ---------------------------------------------------------------------------
// Kernel A: one block per part. Per-tile pipeline:
//   load 16 pts -> h1 (relu, BN folded) -> h2 (relu, BN folded) -> h3 dot in
//   registers (thread = output channel, W3 column in 128 regs) -> running max.
// ---------------------------------------------------------------------------
__global__ __launch_bounds__(256, 1)
void pointnet_kernel(const float* __restrict__ pcls,
                     const float* __restrict__ W1, const float* __restrict__ b1,
                     const float* __restrict__ g1, const float* __restrict__ bt1,
                     const float* __restrict__ W2, const float* __restrict__ b2,
                     const float* __restrict__ g2, const float* __restrict__ bt2,
                     const float* __restrict__ W3, const float* __restrict__ b3,
                     const float* __restrict__ g3, const float* __restrict__ bt3)
{
    __shared__ float sW1[6 * 64];
    __shared__ float sB1[64];
    __shared__ float sW2[64 * 128];
    __shared__ float sB2[128];
    __shared__ float sPts[TILE * 6];
    __shared__ float sH1[TILE * 64];
    __shared__ float sH2[TILE * 128];

    const int tid  = threadIdx.x;      // also = output channel for stage 3
    const int part = blockIdx.x;

    // ---- fold BN into weights/biases (per block; weights are L2-resident) ----
    for (int idx = tid; idx < 6 * 64; idx += 256) {
        int c = idx & 63;
        sW1[idx] = W1[idx] * g1[c];
    }
    if (tid < 64)  sB1[tid] = b1[tid] * g1[tid] + bt1[tid];
    for (int idx = tid; idx < 64 * 128; idx += 256) {
        int c = idx & 127;
        sW2[idx] = W2[idx] * g2[c];
    }
    if (tid < 128) sB2[tid] = b2[tid] * g2[tid] + bt2[tid];

    // W3 column (folded with g3) into registers
    float w3[128];
    const float g3v = g3[tid];
    #pragma unroll
    for (int k = 0; k < 128; k++) w3[k] = W3[k * 256 + tid] * g3v;
    const float b3f = b3[tid] * g3v + bt3[tid];

    float m = -3.402823466e38f;
    const float* pbase = pcls + (size_t)part * (PPTS * 6);

    __syncthreads();

    for (int t = 0; t < NTILES; t++) {
        // load 16 points (96 floats)
        if (tid < TILE * 6) sPts[tid] = pbase[t * TILE * 6 + tid];
        __syncthreads();

        // ---- stage 1: h1[p][c] = relu(pts . W1f + b1f), thread -> (c, 4 points)
        {
            const int c  = tid & 63;
            const int p0 = tid >> 6;              // 0..3
            const float wa = sW1[0 * 64 + c], wb = sW1[1 * 64 + c];
            const float wc = sW1[2 * 64 + c], wd = sW1[3 * 64 + c];
            const float we = sW1[4 * 64 + c], wf = sW1[5 * 64 + c];
            const float bb = sB1[c];
            #pragma unroll
            for (int r = 0; r < 4; r++) {
                const int p = p0 + 4 * r;
                const float* pt = &sPts[p * 6];
                float a = bb + pt[0]*wa + pt[1]*wb + pt[2]*wc
                             + pt[3]*wd + pt[4]*we + pt[5]*wf;
                sH1[p * 64 + c] = fmaxf(a, 0.f);
            }
        }
        __syncthreads();

        // ---- stage 2: h2[p][c] = relu(h1 . W2f + b2f), thread -> (c, 8 points)
        {
            const int c  = tid & 127;
            const int p0 = tid >> 7;              // 0..1
            float acc[8];
            const float bb = sB2[c];
            #pragma unroll
            for (int r = 0; r < 8; r++) acc[r] = bb;
            #pragma unroll
            for (int i4 = 0; i4 < 16; i4++) {
                const float wa = sW2[(4 * i4 + 0) * 128 + c];
                const float wb = sW2[(4 * i4 + 1) * 128 + c];
                const float wc = sW2[(4 * i4 + 2) * 128 + c];
                const float wd = sW2[(4 * i4 + 3) * 128 + c];
                #pragma unroll
                for (int r = 0; r < 8; r++) {
                    const int p = p0 + 2 * r;
                    float4 h = *(const float4*)&sH1[p * 64 + 4 * i4];
                    acc[r] += h.x * wa + h.y * wb + h.z * wc + h.w * wd;
                }
            }
            #pragma unroll
            for (int r = 0; r < 8; r++) {
                const int p = p0 + 2 * r;
                sH2[p * 128 + c] = fmaxf(acc[r], 0.f);
            }
        }
        __syncthreads();

        // ---- stage 3: h3[p][ch] = h2[p] . w3col; max over p (bias after max)
        #pragma unroll 2
        for (int p = 0; p < TILE; p++) {
            const float4* h = (const float4*)&sH2[p * 128];
            float a0 = 0.f, a1 = 0.f, a2 = 0.f, a3 = 0.f;
            #pragma unroll
            for (int k4 = 0; k4 < 32; k4++) {
                float4 hv = h[k4];
                a0 += hv.x * w3[4 * k4 + 0];
                a1 += hv.y * w3[4 * k4 + 1];
                a2 += hv.z * w3[4 * k4 + 2];
                a3 += hv.w * w3[4 * k4 + 3];
            }
            m = fmaxf(m, (a0 + a1) + (a2 + a3));
        }
        __syncthreads();
    }

    g_feat[part * 256 + tid] = m + b3f;
}

// ---------------------------------------------------------------------------
// Kernel B: per-object mean of 16 part features
// ---------------------------------------------------------------------------
__global__ void fmean_kernel()
{
    const int o = blockIdx.x;
    const int c = threadIdx.x;
    float s = 0.f;
    #pragma unroll
    for (int k = 0; k < 16; k++) s += g_feat[(o * 16 + k) * 256 + c];
    g_fmean[o * 256 + c] = s * (1.f / 16.f);
}

// Fold Wc1 (512x256): rows 0..255 (src half) + rows 256..511 (dst half)
__global__ void foldwc1_kernel(const float* __restrict__ Wc1)
{
    const int i = blockIdx.x * 256 + threadIdx.x;   // 0..65535
    g_wc1s[i] = Wc1[i] + Wc1[256 * 256 + i];
}

// ---------------------------------------------------------------------------
// Small GEMM: C[512,256] = act(A[512,256] @ W[256,256] + b). 8 rows / block.
// ---------------------------------------------------------------------------
__global__ __launch_bounds__(256)
void mlp_kernel(const float* __restrict__ A, const float* __restrict__ W,
                const float* __restrict__ b, float* __restrict__ C, int do_relu)
{
    __shared__ float sA[8 * 256];
    const int r0  = blockIdx.x * 8;
    const int tid = threadIdx.x;
    for (int i = tid; i < 8 * 256; i += 256) sA[i] = A[r0 * 256 + i];
    __syncthreads();

    float acc[8];
    #pragma unroll
    for (int r = 0; r < 8; r++) acc[r] = 0.f;

    #pragma unroll 4
    for (int k = 0; k < 256; k++) {
        const float w = W[k * 256 + tid];
        #pragma unroll
        for (int r = 0; r < 8; r++) acc[r] += sA[r * 256 + k] * w;
    }
    const float bb = b[tid];
    #pragma unroll
    for (int r = 0; r < 8; r++) {
        float v = acc[r] + bb;
        if (do_relu) v = fmaxf(v, 0.f);
        C[(r0 + r) * 256 + tid] = v;
    }
}

// ---------------------------------------------------------------------------
// Head: s[o] = tanh(t4[o] . Wc3 + bc3). One warp per row.
// ---------------------------------------------------------------------------
__global__ void head_kernel(const float* __restrict__ Wc3,
                            const float* __restrict__ bc3)
{
    const int w    = threadIdx.x >> 5;
    const int lane = threadIdx.x & 31;
    const int row  = blockIdx.x * 8 + w;
    float a = 0.f;
    #pragma unroll
    for (int k = lane; k < 256; k += 32) a += g_bufA[row * 256 + k] * Wc3[k];
    #pragma unroll
    for (int off = 16; off; off >>= 1) a += __shfl_xor_sync(0xffffffffu, a, off);
    if (lane == 0) g_s[row] = tanhf(a + bc3[0]);
}

// ---------------------------------------------------------------------------
// Output scatter: out[o][i][j] = (i==j) ? 0 : s[o]
// ---------------------------------------------------------------------------
__global__ void out_kernel(float* __restrict__ out)
{
    const int o = blockIdx.x;
    const int t = threadIdx.x;           // 0..255 -> (i, j)
    const int i = t >> 4, j = t & 15;
    out[o * 256 + t] = (i == j) ? 0.f : g_s[o];
}

// ---------------------------------------------------------------------------
extern "C" void kernel_launch(void* const* d_in, const int* in_sizes, int n_in,
                              void* d_out, int out_size)
{
    (void)in_sizes; (void)n_in; (void)out_size;
    const float* pcls = (const float*)d_in[0];
    const float* W1 = (const float*)d_in[1];  const float* b1 = (const float*)d_in[2];
    const float* g1 = (const float*)d_in[3];  const float* bt1 = (const float*)d_in[4];
    const float* W2 = (const float*)d_in[5];  const float* b2 = (const float*)d_in[6];
    const float* g2 = (const float*)d_in[7];  const float* bt2 = (const float*)d_in[8];
    const float* W3 = (const float*)d_in[9];  const float* b3 = (const float*)d_in[10];
    const float* g3 = (const float*)d_in[11]; const float* bt3 = (const float*)d_in[12];
    const float* We = (const float*)d_in[13]; const float* be = (const float*)d_in[14];
    const float* Wg1 = (const float*)d_in[15]; const float* bg1 = (const float*)d_in[16];
    const float* Wg2 = (const float*)d_in[17]; const float* bg2 = (const float*)d_in[18];
    const float* Wc1 = (const float*)d_in[19]; const float* bc1 = (const float*)d_in[20];
    const float* Wc2 = (const float*)d_in[21]; const float* bc2 = (const float*)d_in[22];
    const float* Wc3 = (const float*)d_in[23]; const float* bc3 = (const float*)d_in[24];
    // d_in[25..29] = edge arrays: structure is the dense intra-object graph, used implicitly.

    float *p_fmean, *p_bufA, *p_bufB, *p_wc1s;
    cudaGetSymbolAddress((void**)&p_fmean, g_fmean);
    cudaGetSymbolAddress((void**)&p_bufA,  g_bufA);
    cudaGetSymbolAddress((void**)&p_bufB,  g_bufB);
    cudaGetSymbolAddress((void**)&p_wc1s,  g_wc1s);

    pointnet_kernel<<<PARTS, 256>>>(pcls, W1, b1, g1, bt1,
                                    W2, b2, g2, bt2, W3, b3, g3, bt3);
    fmean_kernel<<<NOBJ, 256>>>();
    foldwc1_kernel<<<256, 256>>>(Wc1);

    // t0 = fmean @ We + be            (object_embedding, mean commutes)
    mlp_kernel<<<64, 256>>>(p_fmean, We, be, p_bufA, 0);
    // t1 = relu(t0 @ Wg1 + bg1)       (GCN layer 1 == object mean, constant/obj)
    mlp_kernel<<<64, 256>>>(p_bufA, Wg1, bg1, p_bufB, 1);
    // t2 = t1 @ Wg2 + bg2             (GCN layer 2)
    mlp_kernel<<<64, 256>>>(p_bufB, Wg2, bg2, p_bufA, 0);
    // t3 = relu(t2 @ (Wc1_src + Wc1_dst) + bc1)
    mlp_kernel<<<64, 256>>>(p_bufA, p_wc1s, bc1, p_bufB, 1);
    // t4 = relu(t3 @ Wc2 + bc2)
    mlp_kernel<<<64, 256>>>(p_bufB, Wc2, bc2, p_bufA, 1);
    // s = tanh(t4 . Wc3 + bc3)
    head_kernel<<<64, 256>>>(Wc3, bc3);

    out_kernel<<<NOBJ, 256>>>((float*)d_out);
}

// round 10
// speedup vs baseline: 2.1093x; 2.1093x over previous
#include <cuda_runtime.h>
#include <math.h>
#include <float.h>
#include <stdint.h>

// ---------------------------------------------------------------------------
// Connectivity3D: fused PointNet (6->64->128->256 + BN + maxpool) on tensor
// cores using 3xTF32 emulated-fp32 mma.sync with mask-based operand splitting,
// then the algebraically-collapsed GCN/edge-MLP head (constant per object).
// R6: fix sW1 underfill (rows 4-5 of W1 were read uninitialized in R3-R5).
// R7: identical resubmit (R6 bench died to a container infra failure).
// ---------------------------------------------------------------------------

#define PARTS 8192
#define PPTS  512
#define NOBJ  512
#define TP    32            // points per tile
#define NIT   (PPTS / TP)   // 16 tile iterations

// scratch (device globals: no allocations allowed)
__device__ float g_feat[PARTS * 256];
__device__ float g_fmean[NOBJ * 256];
__device__ float g_bufA[NOBJ * 256];
__device__ float g_bufB[NOBJ * 256];
__device__ float g_wc1s[256 * 256];
__device__ float g_s[NOBJ];

// ---- padded shared layouts (floats); all fragment loads bank-conflict-free
#define LDW2 136   // 64 x 136
#define LDW3 264   // 128 x 264
#define LDH1 68    // 32 x 68
#define LDH2 132   // 32 x 132
#define OFF_W2  0
#define OFF_W3  (OFF_W2 + 64 * LDW2)
#define OFF_H1  (OFF_W3 + 128 * LDW3)
#define OFF_H2  (OFF_H1 + 32 * LDH1)
#define OFF_PTS (OFF_H2 + 32 * LDH2)
#define OFF_W1  (OFF_PTS + TP * 6)
#define OFF_B1  (OFF_W1 + 6 * 64)
#define OFF_B2  (OFF_B1 + 64)
#define SMEM_FLOATS (OFF_B2 + 128)
#define SMEM_BYTES  (SMEM_FLOATS * 4)         // 198656 B

// Mask-based fp32 -> (hi, lo) split. hi keeps sign+exp+top 10 mantissa bits
// (exactly representable in tf32); lo = x - hi is exact (Sterbenz).
__device__ __forceinline__ void tfsplit(float x, unsigned& hi, unsigned& lo) {
    unsigned xb = __float_as_uint(x);
    hi = xb & 0xFFFFE000u;
    lo = __float_as_uint(x - __uint_as_float(hi));
}

__device__ __forceinline__ void mma8(float c[4], const unsigned a[4], const unsigned b[2]) {
    asm volatile("mma.sync.aligned.m16n8k8.row.col.f32.tf32.tf32.f32 "
                 "{%0,%1,%2,%3}, {%4,%5,%6,%7}, {%8,%9}, {%0,%1,%2,%3};"
                 : "+f"(c[0]), "+f"(c[1]), "+f"(c[2]), "+f"(c[3])
                 : "r"(a[0]), "r"(a[1]), "r"(a[2]), "r"(a[3]),
                   "r"(b[0]), "r"(b[1]));
}

// 3xTF32: C += Al*Bh + Ah*Bl + Ah*Bh   (Al*Bl term ~2^-26, dropped)
__device__ __forceinline__ void mma3(float c[4],
                                     const unsigned ah[4], const unsigned al[4],
                                     const unsigned bh[2], const unsigned bl[2]) {
    mma8(c, al, bh);
    mma8(c, ah, bl);
    mma8(c, ah, bh);
}

// ---------------------------------------------------------------------------
// Kernel A: one block (256 thr = 8 warps) per part.
// ---------------------------------------------------------------------------
__global__ __launch_bounds__(256, 1)
void pointnet_mma_kernel(const float* __restrict__ pcls,
                         const float* __restrict__ W1, const float* __restrict__ b1,
                         const float* __restrict__ g1, const float* __restrict__ bt1,
                         const float* __restrict__ W2, const float* __restrict__ b2,
                         const float* __restrict__ g2, const float* __restrict__ bt2,
                         const float* __restrict__ W3, const float* __restrict__ b3,
                         const float* __restrict__ g3, const float* __restrict__ bt3)
{
    extern __shared__ float sm[];
    float* sW2 = sm + OFF_W2;
    float* sW3 = sm + OFF_W3;
    float* sH1 = sm + OFF_H1;
    float* sH2 = sm + OFF_H2;
    float* sPt = sm + OFF_PTS;
    float* sW1 = sm + OFF_W1;
    float* sB1 = sm + OFF_B1;
    float* sB2 = sm + OFF_B2;

    const int tid  = threadIdx.x;
    const int w    = tid >> 5;
    const int lane = tid & 31;
    const int g    = lane >> 2;   // 0..7
    const int tg   = lane & 3;    // 0..3
    const int part = blockIdx.x;

    // ---- fold BN into weights (fp32; split happens at fragment load) ----
    for (int i = tid; i < 64 * 128; i += 256) {
        int c = i & 127;
        sW2[(i >> 7) * LDW2 + c] = W2[i] * __ldg(&g2[c]);
    }
    for (int i = tid; i < 128 * 256; i += 256) {
        int c = i & 255;
        sW3[(i >> 8) * LDW3 + c] = W3[i] * __ldg(&g3[c]);
    }
    // R6 FIX: grid-stride fill covers all 384 elements (blockDim is only 256;
    // the old `if (tid < 384)` left rows 4-5 of W1 uninitialized).
    for (int i = tid; i < 6 * 64; i += 256) {
        int c = i & 63;
        sW1[i] = W1[i] * __ldg(&g1[c]);
    }
    if (tid < 64)  sB1[tid] = b1[tid] * g1[tid] + bt1[tid];
    if (tid >= 64 && tid < 192) { int c = tid - 64; sB2[c] = b2[c] * g2[c] + bt2[c]; }

    const int c1 = tid & 63;
    const int pg = tid >> 6;   // 0..3 -> 8 points each
    __syncthreads();
    float w1r[6];
    #pragma unroll
    for (int d = 0; d < 6; d++) w1r[d] = sW1[d * 64 + c1];
    const float b1f = sB1[c1];

    const int nb2 = (w >> 1) * 32;   // stage-2 channel base
    const int nb3 = w * 32;          // stage-3 channel base
    const int m0  = (w & 1) * 16;    // stage-2 mtile

    float run[4][4];
    #pragma unroll
    for (int nt = 0; nt < 4; nt++)
        #pragma unroll
        for (int j = 0; j < 4; j++) run[nt][j] = -FLT_MAX;

    const float* pbase = pcls + (size_t)part * (PPTS * 6);

    for (int t = 0; t < NIT; t++) {
        // ---- load 32 points ----
        if (tid < TP * 6) sPt[tid] = pbase[t * TP * 6 + tid];
        __syncthreads();

        // ---- stage 1 (fp32 SIMT): H1[32,64] ----
        #pragma unroll
        for (int r = 0; r < 8; r++) {
            const int p = pg * 8 + r;
            const float* pt = &sPt[p * 6];
            float a = b1f + pt[0]*w1r[0] + pt[1]*w1r[1] + pt[2]*w1r[2]
                          + pt[3]*w1r[3] + pt[4]*w1r[4] + pt[5]*w1r[5];
            sH1[p * LDH1 + c1] = fmaxf(a, 0.f);
        }
        __syncthreads();

        // ---- stage 2 (3xTF32): H2[32,128] = relu(H1 @ W2f + b2f) ----
        {
            float c2[4][4];
            #pragma unroll
            for (int nt = 0; nt < 4; nt++)
                #pragma unroll
                for (int j = 0; j < 4; j++) c2[nt][j] = 0.f;

            #pragma unroll
            for (int kt = 0; kt < 8; kt++) {
                unsigned ah[4], al[4];
                const float* ab = &sH1[(m0 + g) * LDH1 + kt * 8 + tg];
                tfsplit(ab[0],              ah[0], al[0]);
                tfsplit(ab[8 * LDH1],       ah[1], al[1]);
                tfsplit(ab[4],              ah[2], al[2]);
                tfsplit(ab[8 * LDH1 + 4],   ah[3], al[3]);
                #pragma unroll
                for (int nt = 0; nt < 4; nt++) {
                    unsigned bh[2], bl[2];
                    const float* bp = &sW2[(kt * 8 + tg) * LDW2 + nb2 + nt * 8 + g];
                    tfsplit(bp[0],          bh[0], bl[0]);
                    tfsplit(bp[4 * LDW2],   bh[1], bl[1]);
                    mma3(c2[nt], ah, al, bh, bl);
                }
            }
            #pragma unroll
            for (int nt = 0; nt < 4; nt++) {
                const int n = nb2 + nt * 8 + 2 * tg;
                float v0 = fmaxf(c2[nt][0] + sB2[n],     0.f);
                float v1 = fmaxf(c2[nt][1] + sB2[n + 1], 0.f);
                float v2 = fmaxf(c2[nt][2] + sB2[n],     0.f);
                float v3 = fmaxf(c2[nt][3] + sB2[n + 1], 0.f);
                *(float2*)&sH2[(m0 + g) * LDH2 + n]     = make_float2(v0, v1);
                *(float2*)&sH2[(m0 + g + 8) * LDH2 + n] = make_float2(v2, v3);
            }
        }
        __syncthreads();

        // ---- stage 3 (3xTF32): H3[32,256] = H2 @ W3f; running max ----
        {
            float d[2][4][4];
            #pragma unroll
            for (int mt = 0; mt < 2; mt++)
                #pragma unroll
                for (int nt = 0; nt < 4; nt++)
                    #pragma unroll
                    for (int j = 0; j < 4; j++) d[mt][nt][j] = 0.f;

            #pragma unroll
            for (int kt = 0; kt < 16; kt++) {
                unsigned ah[2][4], al[2][4];
                #pragma unroll
                for (int mt = 0; mt < 2; mt++) {
                    const float* ab = &sH2[(mt * 16 + g) * LDH2 + kt * 8 + tg];
                    tfsplit(ab[0],            ah[mt][0], al[mt][0]);
                    tfsplit(ab[8 * LDH2],     ah[mt][1], al[mt][1]);
                    tfsplit(ab[4],            ah[mt][2], al[mt][2]);
                    tfsplit(ab[8 * LDH2 + 4], ah[mt][3], al[mt][3]);
                }
                #pragma unroll
                for (int nt = 0; nt < 4; nt++) {
                    unsigned bh[2], bl[2];
                    const float* bp = &sW3[(kt * 8 + tg) * LDW3 + nb3 + nt * 8 + g];
                    tfsplit(bp[0],          bh[0], bl[0]);
                    tfsplit(bp[4 * LDW3],   bh[1], bl[1]);
                    mma3(d[0][nt], ah[0], al[0], bh, bl);
                    mma3(d[1][nt], ah[1], al[1], bh, bl);
                }
            }
            #pragma unroll
            for (int nt = 0; nt < 4; nt++)
                #pragma unroll
                for (int j = 0; j < 4; j++)
                    run[nt][j] = fmaxf(run[nt][j], fmaxf(d[0][nt][j], d[1][nt][j]));
        }
        __syncthreads();
    }

    // ---- reduce max across rows, add folded stage-3 bias, write feature ----
    #pragma unroll
    for (int nt = 0; nt < 4; nt++) {
        float e = fmaxf(run[nt][0], run[nt][2]);   // col 2*tg
        float o = fmaxf(run[nt][1], run[nt][3]);   // col 2*tg+1
        #pragma unroll
        for (int off = 4; off <= 16; off <<= 1) {
            e = fmaxf(e, __shfl_xor_sync(0xffffffffu, e, off));
            o = fmaxf(o, __shfl_xor_sync(0xffffffffu, o, off));
        }
        if (g == 0) {
            const int ce = nb3 + nt * 8 + 2 * tg;
            const int co = ce + 1;
            g_feat[part * 256 + ce] = e + (__ldg(&b3[ce]) * __ldg(&g3[ce]) + __ldg(&bt3[ce]));
            g_feat[part * 256 + co] = o + (__ldg(&b3[co]) * __ldg(&g3[co]) + __ldg(&bt3[co]));
        }
    }
}

// ---------------------------------------------------------------------------
__global__ void fmean_kernel()
{
    const int o = blockIdx.x;
    const int c = threadIdx.x;
    float s = 0.f;
    #pragma unroll
    for (int k = 0; k < 16; k++) s += g_feat[(o * 16 + k) * 256 + c];
    g_fmean[o * 256 + c] = s * (1.f / 16.f);
}

__global__ void foldwc1_kernel(const float* __restrict__ Wc1)
{
    const int i = blockIdx.x * 256 + threadIdx.x;
    g_wc1s[i] = Wc1[i] + Wc1[256 * 256 + i];
}

// ---------------------------------------------------------------------------
// C[512,256] = act(A @ W + b). One block per row; thread = output column.
// ---------------------------------------------------------------------------
__global__ __launch_bounds__(256)
void mlp_kernel(const float* __restrict__ A, const float* __restrict__ W,
                const float* __restrict__ b, float* __restrict__ C, int do_relu)
{
    __shared__ float sA[256];
    const int row = blockIdx.x;
    const int tid = threadIdx.x;
    sA[tid] = A[row * 256 + tid];
    __syncthreads();

    float acc = 0.f;
    #pragma unroll 8
    for (int k = 0; k < 256; k++) acc += sA[k] * W[k * 256 + tid];
    float v = acc + b[tid];
    if (do_relu) v = fmaxf(v, 0.f);
    C[row * 256 + tid] = v;
}

__global__ void head_kernel(const float* __restrict__ Wc3,
                            const float* __restrict__ bc3)
{
    const int w    = threadIdx.x >> 5;
    const int lane = threadIdx.x & 31;
    const int row  = blockIdx.x * 8 + w;
    float a = 0.f;
    #pragma unroll
    for (int k = lane; k < 256; k += 32) a += g_bufA[row * 256 + k] * Wc3[k];
    #pragma unroll
    for (int off = 16; off; off >>= 1) a += __shfl_xor_sync(0xffffffffu, a, off);
    if (lane == 0) g_s[row] = tanhf(a + bc3[0]);
}

__global__ void out_kernel(float* __restrict__ out)
{
    const int o = blockIdx.x;
    const int t = threadIdx.x;
    const int i = t >> 4, j = t & 15;
    out[o * 256 + t] = (i == j) ? 0.f : g_s[o];
}

// ---------------------------------------------------------------------------
extern "C" void kernel_launch(void* const* d_in, const int* in_sizes, int n_in,
                              void* d_out, int out_size)
{
    (void)in_sizes; (void)n_in; (void)out_size;
    const float* pcls = (const float*)d_in[0];
    const float* W1 = (const float*)d_in[1];  const float* b1 = (const float*)d_in[2];
    const float* g1 = (const float*)d_in[3];  const float* bt1 = (const float*)d_in[4];
    const float* W2 = (const float*)d_in[5];  const float* b2 = (const float*)d_in[6];
    const float* g2 = (const float*)d_in[7];  const float* bt2 = (const float*)d_in[8];
    const float* W3 = (const float*)d_in[9];  const float* b3 = (const float*)d_in[10];
    const float* g3 = (const float*)d_in[11]; const float* bt3 = (const float*)d_in[12];
    const float* We = (const float*)d_in[13]; const float* be = (const float*)d_in[14];
    const float* Wg1 = (const float*)d_in[15]; const float* bg1 = (const float*)d_in[16];
    const float* Wg2 = (const float*)d_in[17]; const float* bg2 = (const float*)d_in[18];
    const float* Wc1 = (const float*)d_in[19]; const float* bc1 = (const float*)d_in[20];
    const float* Wc2 = (const float*)d_in[21]; const float* bc2 = (const float*)d_in[22];
    const float* Wc3 = (const float*)d_in[23]; const float* bc3 = (const float*)d_in[24];

    float *p_fmean, *p_bufA, *p_bufB, *p_wc1s;
    cudaGetSymbolAddress((void**)&p_fmean, g_fmean);
    cudaGetSymbolAddress((void**)&p_bufA,  g_bufA);
    cudaGetSymbolAddress((void**)&p_bufB,  g_bufB);
    cudaGetSymbolAddress((void**)&p_wc1s,  g_wc1s);

    cudaFuncSetAttribute(pointnet_mma_kernel,
                         cudaFuncAttributeMaxDynamicSharedMemorySize, SMEM_BYTES);

    pointnet_mma_kernel<<<PARTS, 256, SMEM_BYTES>>>(pcls, W1, b1, g1, bt1,
                                                    W2, b2, g2, bt2,
                                                    W3, b3, g3, bt3);
    fmean_kernel<<<NOBJ, 256>>>();
    foldwc1_kernel<<<256, 256>>>(Wc1);

    mlp_kernel<<<NOBJ, 256>>>(p_fmean, We, be, p_bufA, 0);
    mlp_kernel<<<NOBJ, 256>>>(p_bufA, Wg1, bg1, p_bufB, 1);
    mlp_kernel<<<NOBJ, 256>>>(p_bufB, Wg2, bg2, p_bufA, 0);
    mlp_kernel<<<NOBJ, 256>>>(p_bufA, p_wc1s, bc1, p_bufB, 1);
    mlp_kernel<<<NOBJ, 256>>>(p_bufB, Wc2, bc2, p_bufA, 1);
    head_kernel<<<64, 256>>>(Wc3, bc3);

    out_kernel<<<NOBJ, 256>>>((float*)d_out);
}

// round 11
// speedup vs baseline: 3.1842x; 1.5096x over previous
#include <cuda_runtime.h>
#include <cuda_bf16.h>
#include <math.h>
#include <float.h>
#include <stdint.h>

// ---------------------------------------------------------------------------
// Connectivity3D: fused PointNet (6->64->128->256 + BN + maxpool) on tensor
// cores using 3-pass bf16-split (hi+lo) m16n8k16 mma.sync (fp32 accum),
// then the algebraically-collapsed GCN/edge-MLP head (constant per object).
// R11: tf32 k8 x3 -> bf16 k16 x3. Weights split hi/lo once in prologue;
// activations split once at production. Packed bf16x2 smem words match the
// k16 fragment register layout: 1 LDS = 1 fragment reg, no in-loop splits.
// ---------------------------------------------------------------------------

#define PARTS 8192
#define PPTS  512
#define NOBJ  512
#define TP    32            // points per tile
#define NIT   (PPTS / TP)   // 16 tile iterations

// scratch (device globals: no allocations allowed)
__device__ float g_feat[PARTS * 256];
__device__ float g_fmean[NOBJ * 256];
__device__ float g_bufA[NOBJ * 256];
__device__ float g_bufB[NOBJ * 256];
__device__ float g_wc1s[256 * 256];
__device__ float g_s[NOBJ];

// ---- packed-word shared layout (32-bit words, each = bf16x2 along k) ----
// A-arrays need LD = 4 (mod 32), B-arrays LD = 8 (mod 32) for conflict-free
// fragment loads (lanes map (g,tg) -> g*LD + tg resp. tg*LD + g banks).
#define LDW2W 136   // W2: 32 kp-words x 136 cols   (136 % 32 == 8)
#define LDW3W 264   // W3: 64 kp-words x 264 cols   (264 % 32 == 8)
#define LDH1W 36    // H1: 32 rows x 36 kp-words    ( 36 % 32 == 4)
#define LDH2W 68    // H2: 32 rows x 68 kp-words    ( 68 % 32 == 4)

#define OFF_W2H 0
#define OFF_W2L (OFF_W2H + 32 * LDW2W)      // 4352
#define OFF_W3H (OFF_W2L + 32 * LDW2W)      // 8704
#define OFF_W3L (OFF_W3H + 64 * LDW3W)      // 25600
#define OFF_H1H (OFF_W3L + 64 * LDW3W)      // 42496
#define OFF_H1L (OFF_H1H + 32 * LDH1W)      // 43648
#define OFF_H2H (OFF_H1L + 32 * LDH1W)      // 44800
#define OFF_H2L (OFF_H2H + 32 * LDH2W)      // 46976
#define OFF_PTS (OFF_H2L + 32 * LDH2W)      // 49152 (float words)
#define OFF_W1  (OFF_PTS + TP * 6)
#define OFF_B1  (OFF_W1 + 6 * 64)
#define OFF_B2  (OFF_B1 + 64)
#define SMEM_WORDS (OFF_B2 + 128)           // 49920
#define SMEM_BYTES (SMEM_WORDS * 4)         // 199680 B

// split one fp32 into (hi, lo) bf16: hi = rn(x), lo = rn(x - hi). Combined
// coverage ~16-17 mantissa bits; dropped lo*lo product term ~2^-18 relative.
__device__ __forceinline__ void bfsplit1(float x, __nv_bfloat16& h, __nv_bfloat16& l) {
    h = __float2bfloat16_rn(x);
    l = __float2bfloat16_rn(x - __bfloat162float(h));
}

// split two fp32 (adjacent k) into packed hi-word and lo-word
__device__ __forceinline__ void pack2(float x0, float x1, unsigned& hi, unsigned& lo) {
    __nv_bfloat16 h0, l0, h1, l1;
    bfsplit1(x0, h0, l0);
    bfsplit1(x1, h1, l1);
    __nv_bfloat162 hp = __halves2bfloat162(h0, h1);   // .x = low 16b = even k
    __nv_bfloat162 lp = __halves2bfloat162(l0, l1);
    hi = *reinterpret_cast<unsigned*>(&hp);
    lo = *reinterpret_cast<unsigned*>(&lp);
}

__device__ __forceinline__ void mma16(float c[4], const unsigned a[4], const unsigned b[2]) {
    asm volatile("mma.sync.aligned.m16n8k16.row.col.f32.bf16.bf16.f32 "
                 "{%0,%1,%2,%3}, {%4,%5,%6,%7}, {%8,%9}, {%0,%1,%2,%3};"
                 : "+f"(c[0]), "+f"(c[1]), "+f"(c[2]), "+f"(c[3])
                 : "r"(a[0]), "r"(a[1]), "r"(a[2]), "r"(a[3]),
                   "r"(b[0]), "r"(b[1]));
}

// 3-pass bf16: C += Ah*Bh + Ah*Bl + Al*Bh  (Al*Bl ~2^-18, dropped)
__device__ __forceinline__ void mma3(float c[4],
                                     const unsigned ah[4], const unsigned al[4],
                                     const unsigned bh[2], const unsigned bl[2]) {
    mma16(c, ah, bh);
    mma16(c, ah, bl);
    mma16(c, al, bh);
}

// ---------------------------------------------------------------------------
// Kernel A: one block (256 thr = 8 warps) per part.
// ---------------------------------------------------------------------------
__global__ __launch_bounds__(256, 1)
void pointnet_mma_kernel(const float* __restrict__ pcls,
                         const float* __restrict__ W1, const float* __restrict__ b1,
                         const float* __restrict__ g1, const float* __restrict__ bt1,
                         const float* __restrict__ W2, const float* __restrict__ b2,
                         const float* __restrict__ g2, const float* __restrict__ bt2,
                         const float* __restrict__ W3, const float* __restrict__ b3,
                         const float* __restrict__ g3, const float* __restrict__ bt3)
{
    extern __shared__ unsigned smw[];
    unsigned* sW2h = smw + OFF_W2H;
    unsigned* sW2l = smw + OFF_W2L;
    unsigned* sW3h = smw + OFF_W3H;
    unsigned* sW3l = smw + OFF_W3L;
    unsigned* sH1h = smw + OFF_H1H;
    unsigned* sH1l = smw + OFF_H1L;
    unsigned* sH2h = smw + OFF_H2H;
    unsigned* sH2l = smw + OFF_H2L;
    float* sPt = reinterpret_cast<float*>(smw + OFF_PTS);
    float* sW1 = reinterpret_cast<float*>(smw + OFF_W1);
    float* sB1 = reinterpret_cast<float*>(smw + OFF_B1);
    float* sB2 = reinterpret_cast<float*>(smw + OFF_B2);
    __nv_bfloat16* sW2h_b = reinterpret_cast<__nv_bfloat16*>(sW2h);
    __nv_bfloat16* sW2l_b = reinterpret_cast<__nv_bfloat16*>(sW2l);
    __nv_bfloat16* sW3h_b = reinterpret_cast<__nv_bfloat16*>(sW3h);
    __nv_bfloat16* sW3l_b = reinterpret_cast<__nv_bfloat16*>(sW3l);
    __nv_bfloat16* sH1h_b = reinterpret_cast<__nv_bfloat16*>(sH1h);
    __nv_bfloat16* sH1l_b = reinterpret_cast<__nv_bfloat16*>(sH1l);

    const int tid  = threadIdx.x;
    const int w    = tid >> 5;
    const int lane = tid & 31;
    const int g    = lane >> 2;   // 0..7
    const int tg   = lane & 3;    // 0..3
    const int part = blockIdx.x;

    // ---- prologue: fold BN, split hi/lo ONCE, pack along k ----
    // B-layout: word(kp, n) at kp*LD + n, word = {k=2kp (lo16), k=2kp+1 (hi16)}
    for (int i = tid; i < 64 * 128; i += 256) {
        int k = i >> 7, c = i & 127;
        float v = W2[i] * __ldg(&g2[c]);
        __nv_bfloat16 h, l;
        bfsplit1(v, h, l);
        int bi = ((k >> 1) * LDW2W + c) * 2 + (k & 1);
        sW2h_b[bi] = h;
        sW2l_b[bi] = l;
    }
    for (int i = tid; i < 128 * 256; i += 256) {
        int k = i >> 8, c = i & 255;
        float v = W3[i] * __ldg(&g3[c]);
        __nv_bfloat16 h, l;
        bfsplit1(v, h, l);
        int bi = ((k >> 1) * LDW3W + c) * 2 + (k & 1);
        sW3h_b[bi] = h;
        sW3l_b[bi] = l;
    }
    for (int i = tid; i < 6 * 64; i += 256) {   // grid-stride: covers all 384
        int c = i & 63;
        sW1[i] = W1[i] * __ldg(&g1[c]);
    }
    if (tid < 64)  sB1[tid] = b1[tid] * g1[tid] + bt1[tid];
    if (tid >= 64 && tid < 192) { int c = tid - 64; sB2[c] = b2[c] * g2[c] + bt2[c]; }

    const int c1 = tid & 63;
    const int pg = tid >> 6;   // 0..3 -> 8 points each
    __syncthreads();
    float w1r[6];
    #pragma unroll
    for (int d = 0; d < 6; d++) w1r[d] = sW1[d * 64 + c1];
    const float b1f = sB1[c1];

    const int nb2 = (w >> 1) * 32;   // stage-2 channel base
    const int nb3 = w * 32;          // stage-3 channel base
    const int m0  = (w & 1) * 16;    // stage-2 mtile

    float run[4][4];
    #pragma unroll
    for (int nt = 0; nt < 4; nt++)
        #pragma unroll
        for (int j = 0; j < 4; j++) run[nt][j] = -FLT_MAX;

    const float* pbase = pcls + (size_t)part * (PPTS * 6);

    for (int t = 0; t < NIT; t++) {
        // ---- load 32 points ----
        if (tid < TP * 6) sPt[tid] = pbase[t * TP * 6 + tid];
        __syncthreads();

        // ---- stage 1 (fp32 SIMT): H1[32,64], stored split bf16 ----
        #pragma unroll
        for (int r = 0; r < 8; r++) {
            const int p = pg * 8 + r;
            const float* pt = &sPt[p * 6];
            float a = b1f + pt[0]*w1r[0] + pt[1]*w1r[1] + pt[2]*w1r[2]
                          + pt[3]*w1r[3] + pt[4]*w1r[4] + pt[5]*w1r[5];
            a = fmaxf(a, 0.f);
            __nv_bfloat16 h, l;
            bfsplit1(a, h, l);
            const int bi = p * (LDH1W * 2) + c1;
            sH1h_b[bi] = h;
            sH1l_b[bi] = l;
        }
        __syncthreads();

        // ---- stage 2 (bf16x3 k16): H2[32,128] = relu(H1 @ W2f + b2f) ----
        {
            float c2[4][4];
            #pragma unroll
            for (int nt = 0; nt < 4; nt++)
                #pragma unroll
                for (int j = 0; j < 4; j++) c2[nt][j] = 0.f;

            #pragma unroll
            for (int kt = 0; kt < 4; kt++) {          // 4 x k16 = K64
                unsigned ah[4], al[4];
                const unsigned* ph = &sH1h[(m0 + g) * LDH1W + kt * 8 + tg];
                const unsigned* pl = &sH1l[(m0 + g) * LDH1W + kt * 8 + tg];
                ah[0] = ph[0]; ah[1] = ph[8 * LDH1W]; ah[2] = ph[4]; ah[3] = ph[8 * LDH1W + 4];
                al[0] = pl[0]; al[1] = pl[8 * LDH1W]; al[2] = pl[4]; al[3] = pl[8 * LDH1W + 4];
                #pragma unroll
                for (int nt = 0; nt < 4; nt++) {
                    unsigned bh[2], bl[2];
                    const unsigned* qh = &sW2h[(kt * 8 + tg) * LDW2W + nb2 + nt * 8 + g];
                    const unsigned* ql = &sW2l[(kt * 8 + tg) * LDW2W + nb2 + nt * 8 + g];
                    bh[0] = qh[0]; bh[1] = qh[4 * LDW2W];
                    bl[0] = ql[0]; bl[1] = ql[4 * LDW2W];
                    mma3(c2[nt], ah, al, bh, bl);
                }
            }
            #pragma unroll
            for (int nt = 0; nt < 4; nt++) {
                const int n = nb2 + nt * 8 + 2 * tg;
                float v0 = fmaxf(c2[nt][0] + sB2[n],     0.f);
                float v1 = fmaxf(c2[nt][1] + sB2[n + 1], 0.f);
                float v2 = fmaxf(c2[nt][2] + sB2[n],     0.f);
                float v3 = fmaxf(c2[nt][3] + sB2[n + 1], 0.f);
                unsigned h0, l0, h1, l1;
                pack2(v0, v1, h0, l0);
                pack2(v2, v3, h1, l1);
                const int wcol = ((nb2 + nt * 8) >> 1) + tg;   // = n>>1
                sH2h[(m0 + g) * LDH2W + wcol]     = h0;
                sH2l[(m0 + g) * LDH2W + wcol]     = l0;
                sH2h[(m0 + g + 8) * LDH2W + wcol] = h1;
                sH2l[(m0 + g + 8) * LDH2W + wcol] = l1;
            }
        }
        __syncthreads();

        // ---- stage 3 (bf16x3 k16): H3[32,256] = H2 @ W3f; running max ----
        {
            float d[2][4][4];
            #pragma unroll
            for (int mt = 0; mt < 2; mt++)
                #pragma unroll
                for (int nt = 0; nt < 4; nt++)
                    #pragma unroll
                    for (int j = 0; j < 4; j++) d[mt][nt][j] = 0.f;

            #pragma unroll
            for (int kt = 0; kt < 8; kt++) {          // 8 x k16 = K128
                unsigned ah[2][4], al[2][4];
                #pragma unroll
                for (int mt = 0; mt < 2; mt++) {
                    const unsigned* ph = &sH2h[(mt * 16 + g) * LDH2W + kt * 8 + tg];
                    const unsigned* pl = &sH2l[(mt * 16 + g) * LDH2W + kt * 8 + tg];
                    ah[mt][0] = ph[0]; ah[mt][1] = ph[8 * LDH2W];
                    ah[mt][2] = ph[4]; ah[mt][3] = ph[8 * LDH2W + 4];
                    al[mt][0] = pl[0]; al[mt][1] = pl[8 * LDH2W];
                    al[mt][2] = pl[4]; al[mt][3] = pl[8 * LDH2W + 4];
                }
                #pragma unroll
                for (int nt = 0; nt < 4; nt++) {
                    unsigned bh[2], bl[2];
                    const unsigned* qh = &sW3h[(kt * 8 + tg) * LDW3W + nb3 + nt * 8 + g];
                    const unsigned* ql = &sW3l[(kt * 8 + tg) * LDW3W + nb3 + nt * 8 + g];
                    bh[0] = qh[0]; bh[1] = qh[4 * LDW3W];
                    bl[0] = ql[0]; bl[1] = ql[4 * LDW3W];
                    mma3(d[0][nt], ah[0], al[0], bh, bl);
                    mma3(d[1][nt], ah[1], al[1], bh, bl);
                }
            }
            #pragma unroll
            for (int nt = 0; nt < 4; nt++)
                #pragma unroll
                for (int j = 0; j < 4; j++)
                    run[nt][j] = fmaxf(run[nt][j], fmaxf(d[0][nt][j], d[1][nt][j]));
        }
        __syncthreads();
    }

    // ---- reduce max across rows, add folded stage-3 bias, write feature ----
    #pragma unroll
    for (int nt = 0; nt < 4; nt++) {
        float e = fmaxf(run[nt][0], run[nt][2]);   // col 2*tg
        float o = fmaxf(run[nt][1], run[nt][3]);   // col 2*tg+1
        #pragma unroll
        for (int off = 4; off <= 16; off <<= 1) {
            e = fmaxf(e, __shfl_xor_sync(0xffffffffu, e, off));
            o = fmaxf(o, __shfl_xor_sync(0xffffffffu, o, off));
        }
        if (g == 0) {
            const int ce = nb3 + nt * 8 + 2 * tg;
            const int co = ce + 1;
            g_feat[part * 256 + ce] = e + (__ldg(&b3[ce]) * __ldg(&g3[ce]) + __ldg(&bt3[ce]));
            g_feat[part * 256 + co] = o + (__ldg(&b3[co]) * __ldg(&g3[co]) + __ldg(&bt3[co]));
        }
    }
}

// ---------------------------------------------------------------------------
__global__ void fmean_kernel()
{
    const int o = blockIdx.x;
    const int c = threadIdx.x;
    float s = 0.f;
    #pragma unroll
    for (int k = 0; k < 16; k++) s += g_feat[(o * 16 + k) * 256 + c];
    g_fmean[o * 256 + c] = s * (1.f / 16.f);
}

__global__ void foldwc1_kernel(const float* __restrict__ Wc1)
{
    const int i = blockIdx.x * 256 + threadIdx.x;
    g_wc1s[i] = Wc1[i] + Wc1[256 * 256 + i];
}

// ---------------------------------------------------------------------------
// C[512,256] = act(A @ W + b). One block per row; thread = output column.
// ---------------------------------------------------------------------------
__global__ __launch_bounds__(256)
void mlp_kernel(const float* __restrict__ A, const float* __restrict__ W,
                const float* __restrict__ b, float* __restrict__ C, int do_relu)
{
    __shared__ float sA[256];
    const int row = blockIdx.x;
    const int tid = threadIdx.x;
    sA[tid] = A[row * 256 + tid];
    __syncthreads();

    float acc = 0.f;
    #pragma unroll 8
    for (int k = 0; k < 256; k++) acc += sA[k] * W[k * 256 + tid];
    float v = acc + b[tid];
    if (do_relu) v = fmaxf(v, 0.f);
    C[row * 256 + tid] = v;
}

__global__ void head_kernel(const float* __restrict__ Wc3,
                            const float* __restrict__ bc3)
{
    const int w    = threadIdx.x >> 5;
    const int lane = threadIdx.x & 31;
    const int row  = blockIdx.x * 8 + w;
    float a = 0.f;
    #pragma unroll
    for (int k = lane; k < 256; k += 32) a += g_bufA[row * 256 + k] * Wc3[k];
    #pragma unroll
    for (int off = 16; off; off >>= 1) a += __shfl_xor_sync(0xffffffffu, a, off);
    if (lane == 0) g_s[row] = tanhf(a + bc3[0]);
}

__global__ void out_kernel(float* __restrict__ out)
{
    const int o = blockIdx.x;
    const int t = threadIdx.x;
    const int i = t >> 4, j = t & 15;
    out[o * 256 + t] = (i == j) ? 0.f : g_s[o];
}

// ---------------------------------------------------------------------------
extern "C" void kernel_launch(void* const* d_in, const int* in_sizes, int n_in,
                              void* d_out, int out_size)
{
    (void)in_sizes; (void)n_in; (void)out_size;
    const float* pcls = (const float*)d_in[0];
    const float* W1 = (const float*)d_in[1];  const float* b1 = (const float*)d_in[2];
    const float* g1 = (const float*)d_in[3];  const float* bt1 = (const float*)d_in[4];
    const float* W2 = (const float*)d_in[5];  const float* b2 = (const float*)d_in[6];
    const float* g2 = (const float*)d_in[7];  const float* bt2 = (const float*)d_in[8];
    const float* W3 = (const float*)d_in[9];  const float* b3 = (const float*)d_in[10];
    const float* g3 = (const float*)d_in[11]; const float* bt3 = (const float*)d_in[12];
    const float* We = (const float*)d_in[13]; const float* be = (const float*)d_in[14];
    const float* Wg1 = (const float*)d_in[15]; const float* bg1 = (const float*)d_in[16];
    const float* Wg2 = (const float*)d_in[17]; const float* bg2 = (const float*)d_in[18];
    const float* Wc1 = (const float*)d_in[19]; const float* bc1 = (const float*)d_in[20];
    const float* Wc2 = (const float*)d_in[21]; const float* bc2 = (const float*)d_in[22];
    const float* Wc3 = (const float*)d_in[23]; const float* bc3 = (const float*)d_in[24];

    float *p_fmean, *p_bufA, *p_bufB, *p_wc1s;
    cudaGetSymbolAddress((void**)&p_fmean, g_fmean);
    cudaGetSymbolAddress((void**)&p_bufA,  g_bufA);
    cudaGetSymbolAddress((void**)&p_bufB,  g_bufB);
    cudaGetSymbolAddress((void**)&p_wc1s,  g_wc1s);

    cudaFuncSetAttribute(pointnet_mma_kernel,
                         cudaFuncAttributeMaxDynamicSharedMemorySize, SMEM_BYTES);

    pointnet_mma_kernel<<<PARTS, 256, SMEM_BYTES>>>(pcls, W1, b1, g1, bt1,
                                                    W2, b2, g2, bt2,
                                                    W3, b3, g3, bt3);
    fmean_kernel<<<NOBJ, 256>>>();
    foldwc1_kernel<<<256, 256>>>(Wc1);

    mlp_kernel<<<NOBJ, 256>>>(p_fmean, We, be, p_bufA, 0);
    mlp_kernel<<<NOBJ, 256>>>(p_bufA, Wg1, bg1, p_bufB, 1);
    mlp_kernel<<<NOBJ, 256>>>(p_bufB, Wg2, bg2, p_bufA, 0);
    mlp_kernel<<<NOBJ, 256>>>(p_bufA, p_wc1s, bc1, p_bufB, 1);
    mlp_kernel<<<NOBJ, 256>>>(p_bufB, Wc2, bc2, p_bufA, 1);
    head_kernel<<<64, 256>>>(Wc3, bc3);

    out_kernel<<<NOBJ, 256>>>((float*)d_out);
}

// round 13
// speedup vs baseline: 3.6176x; 1.1361x over previous
#include <cuda_runtime.h>
#include <cuda_bf16.h>
#include <math.h>
#include <float.h>
#include <stdint.h>

// ---------------------------------------------------------------------------
// Connectivity3D: fused PointNet (6->64->128->256 + BN + maxpool) on tensor
// cores using 3-pass bf16-split m16n8k16 mma.sync, then the algebraically-
// collapsed GCN/edge-MLP head (constant per object).
// R12: weights pre-folded/split ONCE in 5 prep kernels (pointnet = launch #6
// so ncu -s 5 captures it); 512 threads (16 warps, 4/SMSP) for latency
// hiding; stage-2 B fragments register-cached; W2 dropped from smem.
// ---------------------------------------------------------------------------

#define PARTS 8192
#define PPTS  512
#define NOBJ  512
#define TP    32
#define NIT   (PPTS / TP)
#define THREADS 512

// packed-word leading dims (32-bit words = bf16x2 along k)
#define LDW2W 136   // 32 kp x 136  (136 % 32 == 8 -> B frags conflict-free)
#define LDW3W 264   // 64 kp x 264  (264 % 32 == 8)
#define LDH1W 36    // 32 rows x 36 ( 36 % 32 == 4 -> A frags conflict-free)
#define LDH2W 68    // 32 rows x 68 ( 68 % 32 == 4)

// scratch (device globals: no allocations allowed)
__device__ float    g_feat[PARTS * 256];
__device__ float    g_fmean[NOBJ * 256];
__device__ float    g_bufA[NOBJ * 256];
__device__ float    g_bufB[NOBJ * 256];
__device__ float    g_wc1s[256 * 256];
__device__ float    g_s[NOBJ];
// prefolded, hi/lo-split, packed weights
__device__ unsigned g_w2h[32 * LDW2W];
__device__ unsigned g_w2l[32 * LDW2W];
__device__ unsigned g_w3h[64 * LDW3W];
__device__ unsigned g_w3l[64 * LDW3W];
__device__ float    g_w1f[6 * 64];
__device__ float    g_b1f[64];
__device__ float    g_b2f[128];
__device__ float    g_b3f[256];

// ---- shared layout (32-bit words) ----
#define OFF_W3H 0
#define OFF_W3L (OFF_W3H + 64 * LDW3W)      // 16896
#define OFF_H1H (OFF_W3L + 64 * LDW3W)      // 33792
#define OFF_H1L (OFF_H1H + 32 * LDH1W)      // 34944
#define OFF_H2H (OFF_H1L + 32 * LDH1W)      // 36096
#define OFF_H2L (OFF_H2H + 32 * LDH2W)      // 38272
#define OFF_PTS (OFF_H2L + 32 * LDH2W)      // 40448
#define OFF_RED (OFF_PTS + TP * 6)          // 40640
#define SMEM_WORDS (OFF_RED + 512)          // 41152
#define SMEM_BYTES (SMEM_WORDS * 4)         // 164608 B

__device__ __forceinline__ void bfsplit1(float x, __nv_bfloat16& h, __nv_bfloat16& l) {
    h = __float2bfloat16_rn(x);
    l = __float2bfloat16_rn(x - __bfloat162float(h));
}

__device__ __forceinline__ void pack2(float x0, float x1, unsigned& hi, unsigned& lo) {
    __nv_bfloat16 h0, l0, h1, l1;
    bfsplit1(x0, h0, l0);
    bfsplit1(x1, h1, l1);
    __nv_bfloat162 hp = __halves2bfloat162(h0, h1);   // .x = low 16b = even k
    __nv_bfloat162 lp = __halves2bfloat162(l0, l1);
    hi = *reinterpret_cast<unsigned*>(&hp);
    lo = *reinterpret_cast<unsigned*>(&lp);
}

__device__ __forceinline__ void mma16(float c[4], const unsigned a[4], const unsigned b[2]) {
    asm volatile("mma.sync.aligned.m16n8k16.row.col.f32.bf16.bf16.f32 "
                 "{%0,%1,%2,%3}, {%4,%5,%6,%7}, {%8,%9}, {%0,%1,%2,%3};"
                 : "+f"(c[0]), "+f"(c[1]), "+f"(c[2]), "+f"(c[3])
                 : "r"(a[0]), "r"(a[1]), "r"(a[2]), "r"(a[3]),
                   "r"(b[0]), "r"(b[1]));
}

__device__ __forceinline__ void mma3(float c[4],
                                     const unsigned ah[4], const unsigned al[4],
                                     const unsigned bh[2], const unsigned bl[2]) {
    mma16(c, ah, bh);
    mma16(c, ah, bl);
    mma16(c, al, bh);
}

// ---------------------------------------------------------------------------
// Prep kernels (one-shot; launches 1-5 so pointnet is launch #6 for ncu -s 5)
// ---------------------------------------------------------------------------
__global__ void foldwc1_kernel(const float* __restrict__ Wc1)
{
    const int i = blockIdx.x * 256 + threadIdx.x;
    g_wc1s[i] = Wc1[i] + Wc1[256 * 256 + i];
}

__global__ void prep_w2_kernel(const float* __restrict__ W2, const float* __restrict__ g2)
{
    const int i = blockIdx.x * 256 + threadIdx.x;   // 8192
    const int k = i >> 7, c = i & 127;
    float v = W2[i] * __ldg(&g2[c]);
    __nv_bfloat16 h, l;
    bfsplit1(v, h, l);
    const int bi = ((k >> 1) * LDW2W + c) * 2 + (k & 1);
    reinterpret_cast<__nv_bfloat16*>(g_w2h)[bi] = h;
    reinterpret_cast<__nv_bfloat16*>(g_w2l)[bi] = l;
}

__global__ void prep_w3a_kernel(const float* __restrict__ W3, const float* __restrict__ g3)
{
    const int i = blockIdx.x * 256 + threadIdx.x;   // 16384 (k 0..63)
    const int k = i >> 8, c = i & 255;
    float v = W3[i] * __ldg(&g3[c]);
    __nv_bfloat16 h, l;
    bfsplit1(v, h, l);
    const int bi = ((k >> 1) * LDW3W + c) * 2 + (k & 1);
    reinterpret_cast<__nv_bfloat16*>(g_w3h)[bi] = h;
    reinterpret_cast<__nv_bfloat16*>(g_w3l)[bi] = l;
}

__global__ void prep_w3b_kernel(const float* __restrict__ W3, const float* __restrict__ g3)
{
    const int i = 16384 + blockIdx.x * 256 + threadIdx.x;   // k 64..127
    const int k = i >> 8, c = i & 255;
    float v = W3[i] * __ldg(&g3[c]);
    __nv_bfloat16 h, l;
    bfsplit1(v, h, l);
    const int bi = ((k >> 1) * LDW3W + c) * 2 + (k & 1);
    reinterpret_cast<__nv_bfloat16*>(g_w3h)[bi] = h;
    reinterpret_cast<__nv_bfloat16*>(g_w3l)[bi] = l;
}

__global__ void prep_w1_kernel(const float* __restrict__ W1, const float* __restrict__ b1,
                               const float* __restrict__ g1, const float* __restrict__ bt1,
                               const float* __restrict__ b2, const float* __restrict__ g2,
                               const float* __restrict__ bt2,
                               const float* __restrict__ b3, const float* __restrict__ g3,
                               const float* __restrict__ bt3)
{
    const int t = threadIdx.x;   // 512
    if (t < 384) g_w1f[t] = W1[t] * g1[t & 63];
    if (t < 64)  g_b1f[t] = b1[t] * g1[t] + bt1[t];
    if (t < 128) g_b2f[t] = b2[t] * g2[t] + bt2[t];
    if (t < 256) g_b3f[t] = b3[t] * g3[t] + bt3[t];
}

// ---------------------------------------------------------------------------
// Kernel A: one block (512 thr = 16 warps) per part.
// ---------------------------------------------------------------------------
__global__ __launch_bounds__(THREADS, 1)
void pointnet_mma_kernel(const float* __restrict__ pcls)
{
    extern __shared__ unsigned smw[];
    unsigned* sW3h = smw + OFF_W3H;
    unsigned* sW3l = smw + OFF_W3L;
    unsigned* sH1h = smw + OFF_H1H;
    unsigned* sH1l = smw + OFF_H1L;
    unsigned* sH2h = smw + OFF_H2H;
    unsigned* sH2l = smw + OFF_H2L;
    float* sPt  = reinterpret_cast<float*>(smw + OFF_PTS);
    float* sRed = reinterpret_cast<float*>(smw + OFF_RED);
    __nv_bfloat16* sH1h_b = reinterpret_cast<__nv_bfloat16*>(sH1h);
    __nv_bfloat16* sH1l_b = reinterpret_cast<__nv_bfloat16*>(sH1l);

    const int tid  = threadIdx.x;
    const int w    = tid >> 5;        // 0..15
    const int lane = tid & 31;
    const int g    = lane >> 2;       // 0..7
    const int tg   = lane & 3;        // 0..3
    const int part = blockIdx.x;

    // ---- prologue: copy prefolded W3 (hi+lo) into smem, uint4-coalesced ----
    {
        const uint4* srcH = reinterpret_cast<const uint4*>(g_w3h);
        const uint4* srcL = reinterpret_cast<const uint4*>(g_w3l);
        uint4* dstH = reinterpret_cast<uint4*>(sW3h);
        uint4* dstL = reinterpret_cast<uint4*>(sW3l);
        #pragma unroll 4
        for (int i = tid; i < (64 * LDW3W) / 4; i += THREADS) {
            dstH[i] = srcH[i];
            dstL[i] = srcL[i];
        }
    }

    // ---- per-thread constants ----
    const int c1 = tid & 63;
    const int pg = tid >> 6;          // 0..7 -> 4 points each
    float w1r[6];
    #pragma unroll
    for (int d = 0; d < 6; d++) w1r[d] = __ldg(&g_w1f[d * 64 + c1]);
    const float b1f = __ldg(&g_b1f[c1]);

    const int m0  = (w & 1) * 16;     // stage-2 m-half
    const int nb2 = (w >> 1) * 16;    // stage-2 col base (2 ntiles)
    const int mt  = w & 1;            // stage-3 m-half
    const int nb3 = (w >> 1) * 32;    // stage-3 col base (4 ntiles)

    // stage-2 B fragments: register-cached once from prefolded gmem
    unsigned b2r[4][2][2][2];         // [kt][nt][hi/lo][reg]
    #pragma unroll
    for (int kt = 0; kt < 4; kt++)
        #pragma unroll
        for (int nt = 0; nt < 2; nt++) {
            const int o = (kt * 8 + tg) * LDW2W + nb2 + nt * 8 + g;
            b2r[kt][nt][0][0] = __ldg(&g_w2h[o]);
            b2r[kt][nt][0][1] = __ldg(&g_w2h[o + 4 * LDW2W]);
            b2r[kt][nt][1][0] = __ldg(&g_w2l[o]);
            b2r[kt][nt][1][1] = __ldg(&g_w2l[o + 4 * LDW2W]);
        }
    // stage-2 biases (fixed columns per thread)
    float bb[2][2];
    #pragma unroll
    for (int nt = 0; nt < 2; nt++) {
        const int n = nb2 + nt * 8 + 2 * tg;
        bb[nt][0] = __ldg(&g_b2f[n]);
        bb[nt][1] = __ldg(&g_b2f[n + 1]);
    }

    float run[4][4];
    #pragma unroll
    for (int nt = 0; nt < 4; nt++)
        #pragma unroll
        for (int j = 0; j < 4; j++) run[nt][j] = -FLT_MAX;

    const float* pbase = pcls + (size_t)part * (PPTS * 6);
    __syncthreads();

    for (int t = 0; t < NIT; t++) {
        // ---- load 32 points ----
        if (tid < TP * 6) sPt[tid] = pbase[t * TP * 6 + tid];
        __syncthreads();

        // ---- stage 1 (fp32 SIMT): H1[32,64] split bf16; 4 points/thread ----
        #pragma unroll
        for (int r = 0; r < 4; r++) {
            const int p = pg * 4 + r;
            const float* pt = &sPt[p * 6];
            float a = b1f + pt[0]*w1r[0] + pt[1]*w1r[1] + pt[2]*w1r[2]
                          + pt[3]*w1r[3] + pt[4]*w1r[4] + pt[5]*w1r[5];
            a = fmaxf(a, 0.f);
            __nv_bfloat16 h, l;
            bfsplit1(a, h, l);
            const int bi = p * (LDH1W * 2) + c1;
            sH1h_b[bi] = h;
            sH1l_b[bi] = l;
        }
        __syncthreads();

        // ---- stage 2 (bf16x3 k16): H2[32,128]; warp = (m-half, 16 cols) ----
        {
            float c2[2][4];
            #pragma unroll
            for (int nt = 0; nt < 2; nt++)
                #pragma unroll
                for (int j = 0; j < 4; j++) c2[nt][j] = 0.f;

            #pragma unroll
            for (int kt = 0; kt < 4; kt++) {
                unsigned ah[4], al[4];
                const unsigned* ph = &sH1h[(m0 + g) * LDH1W + kt * 8 + tg];
                const unsigned* pl = &sH1l[(m0 + g) * LDH1W + kt * 8 + tg];
                ah[0] = ph[0]; ah[1] = ph[8 * LDH1W]; ah[2] = ph[4]; ah[3] = ph[8 * LDH1W + 4];
                al[0] = pl[0]; al[1] = pl[8 * LDH1W]; al[2] = pl[4]; al[3] = pl[8 * LDH1W + 4];
                #pragma unroll
                for (int nt = 0; nt < 2; nt++)
                    mma3(c2[nt], ah, al, b2r[kt][nt][0], b2r[kt][nt][1]);
            }
            #pragma unroll
            for (int nt = 0; nt < 2; nt++) {
                float v0 = fmaxf(c2[nt][0] + bb[nt][0], 0.f);
                float v1 = fmaxf(c2[nt][1] + bb[nt][1], 0.f);
                float v2 = fmaxf(c2[nt][2] + bb[nt][0], 0.f);
                float v3 = fmaxf(c2[nt][3] + bb[nt][1], 0.f);
                unsigned h0, l0, h1, l1;
                pack2(v0, v1, h0, l0);
                pack2(v2, v3, h1, l1);
                const int wcol = (nb2 >> 1) + nt * 4 + tg;
                sH2h[(m0 + g) * LDH2W + wcol]     = h0;
                sH2l[(m0 + g) * LDH2W + wcol]     = l0;
                sH2h[(m0 + g + 8) * LDH2W + wcol] = h1;
                sH2l[(m0 + g + 8) * LDH2W + wcol] = l1;
            }
        }
        __syncthreads();

        // ---- stage 3 (bf16x3 k16): warp = (m-half mt, 32 cols); running max --
        {
            float d[4][4];
            #pragma unroll
            for (int nt = 0; nt < 4; nt++)
                #pragma unroll
                for (int j = 0; j < 4; j++) d[nt][j] = 0.f;

            #pragma unroll
            for (int kt = 0; kt < 8; kt++) {
                unsigned ah[4], al[4];
                const unsigned* ph = &sH2h[(mt * 16 + g) * LDH2W + kt * 8 + tg];
                const unsigned* pl = &sH2l[(mt * 16 + g) * LDH2W + kt * 8 + tg];
                ah[0] = ph[0]; ah[1] = ph[8 * LDH2W]; ah[2] = ph[4]; ah[3] = ph[8 * LDH2W + 4];
                al[0] = pl[0]; al[1] = pl[8 * LDH2W]; al[2] = pl[4]; al[3] = pl[8 * LDH2W + 4];
                #pragma unroll
                for (int nt = 0; nt < 4; nt++) {
                    unsigned bh[2], bl[2];
                    const unsigned* qh = &sW3h[(kt * 8 + tg) * LDW3W + nb3 + nt * 8 + g];
                    const unsigned* ql = &sW3l[(kt * 8 + tg) * LDW3W + nb3 + nt * 8 + g];
                    bh[0] = qh[0]; bh[1] = qh[4 * LDW3W];
                    bl[0] = ql[0]; bl[1] = ql[4 * LDW3W];
                    mma3(d[nt], ah, al, bh, bl);
                }
            }
            #pragma unroll
            for (int nt = 0; nt < 4; nt++)
                #pragma unroll
                for (int j = 0; j < 4; j++)
                    run[nt][j] = fmaxf(run[nt][j], d[nt][j]);
        }
        __syncthreads();
    }

    // ---- per-warp max over its 16 rows -> sRed; combine m-halves ----
    #pragma unroll
    for (int nt = 0; nt < 4; nt++) {
        float e = fmaxf(run[nt][0], run[nt][2]);   // col 2*tg
        float o = fmaxf(run[nt][1], run[nt][3]);   // col 2*tg+1
        #pragma unroll
        for (int off = 4; off <= 16; off <<= 1) {
            e = fmaxf(e, __shfl_xor_sync(0xffffffffu, e, off));
            o = fmaxf(o, __shfl_xor_sync(0xffffffffu, o, off));
        }
        if (g == 0) {
            const int ce = nb3 + nt * 8 + 2 * tg;
            sRed[mt * 256 + ce]     = e;
            sRed[mt * 256 + ce + 1] = o;
        }
    }
    __syncthreads();
    if (mt == 0) {
        const int col = nb3 + lane;
        const float v = fmaxf(sRed[col], sRed[256 + col]) + __ldg(&g_b3f[col]);
        g_feat[part * 256 + col] = v;
    }
}

// ---------------------------------------------------------------------------
__global__ void fmean_kernel()
{
    const int o = blockIdx.x;
    const int c = threadIdx.x;
    float s = 0.f;
    #pragma unroll
    for (int k = 0; k < 16; k++) s += g_feat[(o * 16 + k) * 256 + c];
    g_fmean[o * 256 + c] = s * (1.f / 16.f);
}

// C[512,256] = act(A @ W + b). One block per row; thread = output column.
__global__ __launch_bounds__(256)
void mlp_kernel(const float* __restrict__ A, const float* __restrict__ W,
                const float* __restrict__ b, float* __restrict__ C, int do_relu)
{
    __shared__ float sA[256];
    const int row = blockIdx.x;
    const int tid = threadIdx.x;
    sA[tid] = A[row * 256 + tid];
    __syncthreads();

    float acc = 0.f;
    #pragma unroll 8
    for (int k = 0; k < 256; k++) acc += sA[k] * W[k * 256 + tid];
    float v = acc + b[tid];
    if (do_relu) v = fmaxf(v, 0.f);
    C[row * 256 + tid] = v;
}

__global__ void head_kernel(const float* __restrict__ Wc3,
                            const float* __restrict__ bc3)
{
    const int w    = threadIdx.x >> 5;
    const int lane = threadIdx.x & 31;
    const int row  = blockIdx.x * 8 + w;
    float a = 0.f;
    #pragma unroll
    for (int k = lane; k < 256; k += 32) a += g_bufA[row * 256 + k] * Wc3[k];
    #pragma unroll
    for (int off = 16; off; off >>= 1) a += __shfl_xor_sync(0xffffffffu, a, off);
    if (lane == 0) g_s[row] = tanhf(a + bc3[0]);
}

__global__ void out_kernel(float* __restrict__ out)
{
    const int o = blockIdx.x;
    const int t = threadIdx.x;
    const int i = t >> 4, j = t & 15;
    out[o * 256 + t] = (i == j) ? 0.f : g_s[o];
}

// ---------------------------------------------------------------------------
extern "C" void kernel_launch(void* const* d_in, const int* in_sizes, int n_in,
                              void* d_out, int out_size)
{
    (void)in_sizes; (void)n_in; (void)out_size;
    const float* pcls = (const float*)d_in[0];
    const float* W1 = (const float*)d_in[1];  const float* b1 = (const float*)d_in[2];
    const float* g1 = (const float*)d_in[3];  const float* bt1 = (const float*)d_in[4];
    const float* W2 = (const float*)d_in[5];  const float* b2 = (const float*)d_in[6];
    const float* g2 = (const float*)d_in[7];  const float* bt2 = (const float*)d_in[8];
    const float* W3 = (const float*)d_in[9];  const float* b3 = (const float*)d_in[10];
    const float* g3 = (const float*)d_in[11]; const float* bt3 = (const float*)d_in[12];
    const float* We = (const float*)d_in[13]; const float* be = (const float*)d_in[14];
    const float* Wg1 = (const float*)d_in[15]; const float* bg1 = (const float*)d_in[16];
    const float* Wg2 = (const float*)d_in[17]; const float* bg2 = (const float*)d_in[18];
    const float* Wc1 = (const float*)d_in[19]; const float* bc1 = (const float*)d_in[20];
    const float* Wc2 = (const float*)d_in[21]; const float* bc2 = (const float*)d_in[22];
    const float* Wc3 = (const float*)d_in[23]; const float* bc3 = (const float*)d_in[24];

    float *p_fmean, *p_bufA, *p_bufB, *p_wc1s;
    cudaGetSymbolAddress((void**)&p_fmean, g_fmean);
    cudaGetSymbolAddress((void**)&p_bufA,  g_bufA);
    cudaGetSymbolAddress((void**)&p_bufB,  g_bufB);
    cudaGetSymbolAddress((void**)&p_wc1s,  g_wc1s);

    cudaFuncSetAttribute(pointnet_mma_kernel,
                         cudaFuncAttributeMaxDynamicSharedMemorySize, SMEM_BYTES);

    // launches 1-5: one-shot weight prep (pointnet is launch #6 for ncu -s 5)
    foldwc1_kernel<<<256, 256>>>(Wc1);
    prep_w2_kernel<<<32, 256>>>(W2, g2);
    prep_w3a_kernel<<<64, 256>>>(W3, g3);
    prep_w3b_kernel<<<64, 256>>>(W3, g3);
    prep_w1_kernel<<<1, 512>>>(W1, b1, g1, bt1, b2, g2, bt2, b3, g3, bt3);

    pointnet_mma_kernel<<<PARTS, THREADS, SMEM_BYTES>>>(pcls);

    fmean_kernel<<<NOBJ, 256>>>();
    mlp_kernel<<<NOBJ, 256>>>(p_fmean, We, be, p_bufA, 0);
    mlp_kernel<<<NOBJ, 256>>>(p_bufA, Wg1, bg1, p_bufB, 1);
    mlp_kernel<<<NOBJ, 256>>>(p_bufB, Wg2, bg2, p_bufA, 0);
    mlp_kernel<<<NOBJ, 256>>>(p_bufA, p_wc1s, bc1, p_bufB, 1);
    mlp_kernel<<<NOBJ, 256>>>(p_bufB, Wc2, bc2, p_bufA, 1);
    head_kernel<<<64, 256>>>(Wc3, bc3);
    out_kernel<<<NOBJ, 256>>>((float*)d_out);
}

// round 14
// speedup vs baseline: 4.0936x; 1.1316x over previous
#include <cuda_runtime.h>
#include <cuda_bf16.h>
#include <math.h>
#include <float.h>
#include <stdint.h>

// ---------------------------------------------------------------------------
// Connectivity3D: fused PointNet (6->64->128->256 + BN + maxpool) on tensor
// cores using 3-pass bf16-split m16n8k16 mma.sync, then the algebraically-
// collapsed GCN/edge-MLP head (constant per object).
// R14: TP=64 (half the barriers); each warp owns BOTH m-tiles of its column
// group so B fragments are loaded once per two m-tiles (stage 2 and 3);
// preps merged to 3 kernels so pointnet is launch #4 (ncu lands there).
// ---------------------------------------------------------------------------

#define PARTS 8192
#define PPTS  512
#define NOBJ  512
#define TP    64
#define NIT   (PPTS / TP)   // 8
#define THREADS 512

// packed-word leading dims (32-bit words = bf16x2 along k)
#define LDW2W 136   // 32 kp x 136  (136 % 32 == 8 -> B frags conflict-free)
#define LDW3W 264   // 64 kp x 264  (264 % 32 == 8)
#define LDH1W 36    // 64 rows x 36 ( 36 % 32 == 4 -> A frags conflict-free)
#define LDH2W 68    // 64 rows x 68 ( 68 % 32 == 4)

// scratch (device globals: no allocations allowed)
__device__ float    g_feat[PARTS * 256];
__device__ float    g_fmean[NOBJ * 256];
__device__ float    g_bufA[NOBJ * 256];
__device__ float    g_bufB[NOBJ * 256];
__device__ float    g_wc1s[256 * 256];
__device__ float    g_s[NOBJ];
__device__ unsigned g_w2h[32 * LDW2W];
__device__ unsigned g_w2l[32 * LDW2W];
__device__ unsigned g_w3h[64 * LDW3W];
__device__ unsigned g_w3l[64 * LDW3W];
__device__ float    g_w1f[6 * 64];
__device__ float    g_b1f[64];
__device__ float    g_b2f[128];
__device__ float    g_b3f[256];

// ---- shared layout (32-bit words) ----
#define OFF_W3H 0
#define OFF_W3L (OFF_W3H + 64 * LDW3W)      // 16896
#define OFF_W2H (OFF_W3L + 64 * LDW3W)      // 33792
#define OFF_W2L (OFF_W2H + 32 * LDW2W)      // 38144
#define OFF_H1H (OFF_W2L + 32 * LDW2W)      // 42496
#define OFF_H1L (OFF_H1H + 64 * LDH1W)      // 44800
#define OFF_H2H (OFF_H1L + 64 * LDH1W)      // 47104
#define OFF_H2L (OFF_H2H + 64 * LDH2W)      // 51456
#define OFF_PTS (OFF_H2L + 64 * LDH2W)      // 55808
#define OFF_RED (OFF_PTS + TP * 6)          // 56192
#define SMEM_WORDS (OFF_RED + 512)          // 56704
#define SMEM_BYTES (SMEM_WORDS * 4)         // 226816 B

__device__ __forceinline__ void bfsplit1(float x, __nv_bfloat16& h, __nv_bfloat16& l) {
    h = __float2bfloat16_rn(x);
    l = __float2bfloat16_rn(x - __bfloat162float(h));
}

__device__ __forceinline__ void pack2(float x0, float x1, unsigned& hi, unsigned& lo) {
    __nv_bfloat16 h0, l0, h1, l1;
    bfsplit1(x0, h0, l0);
    bfsplit1(x1, h1, l1);
    __nv_bfloat162 hp = __halves2bfloat162(h0, h1);   // .x = low 16b = even k
    __nv_bfloat162 lp = __halves2bfloat162(l0, l1);
    hi = *reinterpret_cast<unsigned*>(&hp);
    lo = *reinterpret_cast<unsigned*>(&lp);
}

__device__ __forceinline__ void mma16(float c[4], const unsigned a[4], const unsigned b[2]) {
    asm volatile("mma.sync.aligned.m16n8k16.row.col.f32.bf16.bf16.f32 "
                 "{%0,%1,%2,%3}, {%4,%5,%6,%7}, {%8,%9}, {%0,%1,%2,%3};"
                 : "+f"(c[0]), "+f"(c[1]), "+f"(c[2]), "+f"(c[3])
                 : "r"(a[0]), "r"(a[1]), "r"(a[2]), "r"(a[3]),
                   "r"(b[0]), "r"(b[1]));
}

__device__ __forceinline__ void mma3(float c[4],
                                     const unsigned ah[4], const unsigned al[4],
                                     const unsigned bh[2], const unsigned bl[2]) {
    mma16(c, ah, bh);
    mma16(c, ah, bl);
    mma16(c, al, bh);
}

// ---------------------------------------------------------------------------
// Prep kernels (launches 1-3 so pointnet is launch #4, where ncu lands)
// ---------------------------------------------------------------------------
__global__ void prep_misc_kernel(const float* __restrict__ Wc1,
                                 const float* __restrict__ W1, const float* __restrict__ b1,
                                 const float* __restrict__ g1, const float* __restrict__ bt1,
                                 const float* __restrict__ b2, const float* __restrict__ g2,
                                 const float* __restrict__ bt2,
                                 const float* __restrict__ b3, const float* __restrict__ g3,
                                 const float* __restrict__ bt3)
{
    const int i = blockIdx.x * 256 + threadIdx.x;
    g_wc1s[i] = Wc1[i] + Wc1[256 * 256 + i];
    if (blockIdx.x == 0) {
        const int t = threadIdx.x;
        g_w1f[t]       = W1[t]       * g1[t & 63];
        if (t < 128)   g_w1f[t + 256] = W1[t + 256] * g1[t & 63];
        if (t < 64)    g_b1f[t] = b1[t] * g1[t] + bt1[t];
        if (t < 128)   g_b2f[t] = b2[t] * g2[t] + bt2[t];
        g_b3f[t] = b3[t] * g3[t] + bt3[t];
    }
}

__global__ void prep_w2_kernel(const float* __restrict__ W2, const float* __restrict__ g2)
{
    const int i = blockIdx.x * 256 + threadIdx.x;   // 8192
    const int k = i >> 7, c = i & 127;
    float v = W2[i] * __ldg(&g2[c]);
    __nv_bfloat16 h, l;
    bfsplit1(v, h, l);
    const int bi = ((k >> 1) * LDW2W + c) * 2 + (k & 1);
    reinterpret_cast<__nv_bfloat16*>(g_w2h)[bi] = h;
    reinterpret_cast<__nv_bfloat16*>(g_w2l)[bi] = l;
}

__global__ void prep_w3_kernel(const float* __restrict__ W3, const float* __restrict__ g3)
{
    const int i = blockIdx.x * 256 + threadIdx.x;   // 32768
    const int k = i >> 8, c = i & 255;
    float v = W3[i] * __ldg(&g3[c]);
    __nv_bfloat16 h, l;
    bfsplit1(v, h, l);
    const int bi = ((k >> 1) * LDW3W + c) * 2 + (k & 1);
    reinterpret_cast<__nv_bfloat16*>(g_w3h)[bi] = h;
    reinterpret_cast<__nv_bfloat16*>(g_w3l)[bi] = l;
}

// ---------------------------------------------------------------------------
// Kernel A: one block (512 thr = 16 warps) per part; 64-point tiles.
// ---------------------------------------------------------------------------
__global__ __launch_bounds__(THREADS, 1)
void pointnet_mma_kernel(const float* __restrict__ pcls)
{
    extern __shared__ unsigned smw[];
    unsigned* sW3h = smw + OFF_W3H;
    unsigned* sW3l = smw + OFF_W3L;
    unsigned* sW2h = smw + OFF_W2H;
    unsigned* sW2l = smw + OFF_W2L;
    unsigned* sH1h = smw + OFF_H1H;
    unsigned* sH1l = smw + OFF_H1L;
    unsigned* sH2h = smw + OFF_H2H;
    unsigned* sH2l = smw + OFF_H2L;
    float* sPt  = reinterpret_cast<float*>(smw + OFF_PTS);
    float* sRed = reinterpret_cast<float*>(smw + OFF_RED);
    __nv_bfloat16* sH1h_b = reinterpret_cast<__nv_bfloat16*>(sH1h);
    __nv_bfloat16* sH1l_b = reinterpret_cast<__nv_bfloat16*>(sH1l);

    const int tid  = threadIdx.x;
    const int w    = tid >> 5;        // 0..15
    const int lane = tid & 31;
    const int g    = lane >> 2;       // 0..7
    const int tg   = lane & 3;        // 0..3
    const int part = blockIdx.x;

    // ---- prologue: copy prefolded W3 + W2 (hi+lo) into smem, uint4 ----
    {
        const uint4* s3h = reinterpret_cast<const uint4*>(g_w3h);
        const uint4* s3l = reinterpret_cast<const uint4*>(g_w3l);
        uint4* d3h = reinterpret_cast<uint4*>(sW3h);
        uint4* d3l = reinterpret_cast<uint4*>(sW3l);
        #pragma unroll 4
        for (int i = tid; i < (64 * LDW3W) / 4; i += THREADS) {
            d3h[i] = s3h[i];
            d3l[i] = s3l[i];
        }
        const uint4* s2h = reinterpret_cast<const uint4*>(g_w2h);
        const uint4* s2l = reinterpret_cast<const uint4*>(g_w2l);
        uint4* d2h = reinterpret_cast<uint4*>(sW2h);
        uint4* d2l = reinterpret_cast<uint4*>(sW2l);
        #pragma unroll 2
        for (int i = tid; i < (32 * LDW2W) / 4; i += THREADS) {
            d2h[i] = s2h[i];
            d2l[i] = s2l[i];
        }
    }

    // ---- per-thread constants ----
    const int c1 = tid & 63;
    const int pg = tid >> 6;          // 0..7 -> 8 points each
    float w1r[6];
    #pragma unroll
    for (int d = 0; d < 6; d++) w1r[d] = __ldg(&g_w1f[d * 64 + c1]);
    const float b1f = __ldg(&g_b1f[c1]);

    // stage-2 mapping: warp = (mpair = w&1 -> rows mpair*32..+32, cg2 = w>>1 -> 16 cols)
    const int mp2 = (w & 1) * 32;
    const int nb2 = (w >> 1) * 16;    // 2 ntiles
    // stage-3 mapping: warp = (mhalf = w&1 -> rows, cg3 = w>>1 -> 32 cols)
    const int mh3 = (w & 1) * 32;
    const int mhalf = w & 1;
    const int nb3 = (w >> 1) * 32;    // 4 ntiles

    float bb[2][2];
    #pragma unroll
    for (int nt = 0; nt < 2; nt++) {
        const int n = nb2 + nt * 8 + 2 * tg;
        bb[nt][0] = __ldg(&g_b2f[n]);
        bb[nt][1] = __ldg(&g_b2f[n + 1]);
    }

    float run_e[4], run_o[4];
    #pragma unroll
    for (int nt = 0; nt < 4; nt++) { run_e[nt] = -FLT_MAX; run_o[nt] = -FLT_MAX; }

    const float* pbase = pcls + (size_t)part * (PPTS * 6);
    __syncthreads();

    for (int t = 0; t < NIT; t++) {
        // ---- load 64 points (384 floats) ----
        if (tid < TP * 6) sPt[tid] = pbase[t * TP * 6 + tid];
        __syncthreads();

        // ---- stage 1 (fp32 SIMT): H1[64,64] split bf16; 8 points/thread ----
        #pragma unroll
        for (int r = 0; r < 8; r++) {
            const int p = pg * 8 + r;
            const float* pt = &sPt[p * 6];
            float a = b1f + pt[0]*w1r[0] + pt[1]*w1r[1] + pt[2]*w1r[2]
                          + pt[3]*w1r[3] + pt[4]*w1r[4] + pt[5]*w1r[5];
            a = fmaxf(a, 0.f);
            __nv_bfloat16 h, l;
            bfsplit1(a, h, l);
            const int bi = p * (LDH1W * 2) + c1;
            sH1h_b[bi] = h;
            sH1l_b[bi] = l;
        }
        __syncthreads();

        // ---- stage 2 (bf16x3 k16): H2[64,128]; B shared across 2 m-tiles ----
        {
            float c2[2][2][4];
            #pragma unroll
            for (int mt = 0; mt < 2; mt++)
                #pragma unroll
                for (int nt = 0; nt < 2; nt++)
                    #pragma unroll
                    for (int j = 0; j < 4; j++) c2[mt][nt][j] = 0.f;

            #pragma unroll
            for (int kt = 0; kt < 4; kt++) {
                unsigned ah[2][4], al[2][4];
                #pragma unroll
                for (int mt = 0; mt < 2; mt++) {
                    const unsigned* ph = &sH1h[(mp2 + mt * 16 + g) * LDH1W + kt * 8 + tg];
                    const unsigned* pl = &sH1l[(mp2 + mt * 16 + g) * LDH1W + kt * 8 + tg];
                    ah[mt][0] = ph[0]; ah[mt][1] = ph[8 * LDH1W];
                    ah[mt][2] = ph[4]; ah[mt][3] = ph[8 * LDH1W + 4];
                    al[mt][0] = pl[0]; al[mt][1] = pl[8 * LDH1W];
                    al[mt][2] = pl[4]; al[mt][3] = pl[8 * LDH1W + 4];
                }
                #pragma unroll
                for (int nt = 0; nt < 2; nt++) {
                    unsigned bh[2], bl[2];
                    const unsigned* qh = &sW2h[(kt * 8 + tg) * LDW2W + nb2 + nt * 8 + g];
                    const unsigned* ql = &sW2l[(kt * 8 + tg) * LDW2W + nb2 + nt * 8 + g];
                    bh[0] = qh[0]; bh[1] = qh[4 * LDW2W];
                    bl[0] = ql[0]; bl[1] = ql[4 * LDW2W];
                    mma3(c2[0][nt], ah[0], al[0], bh, bl);
                    mma3(c2[1][nt], ah[1], al[1], bh, bl);
                }
            }
            #pragma unroll
            for (int mt = 0; mt < 2; mt++)
                #pragma unroll
                for (int nt = 0; nt < 2; nt++) {
                    float v0 = fmaxf(c2[mt][nt][0] + bb[nt][0], 0.f);
                    float v1 = fmaxf(c2[mt][nt][1] + bb[nt][1], 0.f);
                    float v2 = fmaxf(c2[mt][nt][2] + bb[nt][0], 0.f);
                    float v3 = fmaxf(c2[mt][nt][3] + bb[nt][1], 0.f);
                    unsigned h0, l0, h1, l1;
                    pack2(v0, v1, h0, l0);
                    pack2(v2, v3, h1, l1);
                    const int wcol = (nb2 >> 1) + nt * 4 + tg;
                    const int r0 = mp2 + mt * 16 + g;
                    sH2h[r0 * LDH2W + wcol]       = h0;
                    sH2l[r0 * LDH2W + wcol]       = l0;
                    sH2h[(r0 + 8) * LDH2W + wcol] = h1;
                    sH2l[(r0 + 8) * LDH2W + wcol] = l1;
                }
        }
        __syncthreads();

        // ---- stage 3 (bf16x3 k16): B shared across 2 m-tiles; running max ----
        {
            float d[2][4][4];
            #pragma unroll
            for (int mt = 0; mt < 2; mt++)
                #pragma unroll
                for (int nt = 0; nt < 4; nt++)
                    #pragma unroll
                    for (int j = 0; j < 4; j++) d[mt][nt][j] = 0.f;

            #pragma unroll
            for (int kt = 0; kt < 8; kt++) {
                unsigned ah[2][4], al[2][4];
                #pragma unroll
                for (int mt = 0; mt < 2; mt++) {
                    const unsigned* ph = &sH2h[(mh3 + mt * 16 + g) * LDH2W + kt * 8 + tg];
                    const unsigned* pl = &sH2l[(mh3 + mt * 16 + g) * LDH2W + kt * 8 + tg];
                    ah[mt][0] = ph[0]; ah[mt][1] = ph[8 * LDH2W];
                    ah[mt][2] = ph[4]; ah[mt][3] = ph[8 * LDH2W + 4];
                    al[mt][0] = pl[0]; al[mt][1] = pl[8 * LDH2W];
                    al[mt][2] = pl[4]; al[mt][3] = pl[8 * LDH2W + 4];
                }
                #pragma unroll
                for (int nt = 0; nt < 4; nt++) {
                    unsigned bh[2], bl[2];
                    const unsigned* qh = &sW3h[(kt * 8 + tg) * LDW3W + nb3 + nt * 8 + g];
                    const unsigned* ql = &sW3l[(kt * 8 + tg) * LDW3W + nb3 + nt * 8 + g];
                    bh[0] = qh[0]; bh[1] = qh[4 * LDW3W];
                    bl[0] = ql[0]; bl[1] = ql[4 * LDW3W];
                    mma3(d[0][nt], ah[0], al[0], bh, bl);
                    mma3(d[1][nt], ah[1], al[1], bh, bl);
                }
            }
            #pragma unroll
            for (int nt = 0; nt < 4; nt++) {
                run_e[nt] = fmaxf(run_e[nt],
                            fmaxf(fmaxf(d[0][nt][0], d[0][nt][2]),
                                  fmaxf(d[1][nt][0], d[1][nt][2])));
                run_o[nt] = fmaxf(run_o[nt],
                            fmaxf(fmaxf(d[0][nt][1], d[0][nt][3]),
                                  fmaxf(d[1][nt][1], d[1][nt][3])));
            }
        }
        __syncthreads();
    }

    // ---- warp-level max over point rows -> sRed; combine the 2 m-halves ----
    #pragma unroll
    for (int nt = 0; nt < 4; nt++) {
        float e = run_e[nt], o = run_o[nt];
        #pragma unroll
        for (int off = 4; off <= 16; off <<= 1) {
            e = fmaxf(e, __shfl_xor_sync(0xffffffffu, e, off));
            o = fmaxf(o, __shfl_xor_sync(0xffffffffu, o, off));
        }
        if (g == 0) {
            const int ce = nb3 + nt * 8 + 2 * tg;
            sRed[mhalf * 256 + ce]     = e;
            sRed[mhalf * 256 + ce + 1] = o;
        }
    }
    __syncthreads();
    if (tid < 256) {
        const float v = fmaxf(sRed[tid], sRed[256 + tid]) + __ldg(&g_b3f[tid]);
        g_feat[part * 256 + tid] = v;
    }
}

// ---------------------------------------------------------------------------
__global__ void fmean_kernel()
{
    const int o = blockIdx.x;
    const int c = threadIdx.x;
    float s = 0.f;
    #pragma unroll
    for (int k = 0; k < 16; k++) s += g_feat[(o * 16 + k) * 256 + c];
    g_fmean[o * 256 + c] = s * (1.f / 16.f);
}

// C[512,256] = act(A @ W + b). One block per row; thread = output column.
__global__ __launch_bounds__(256)
void mlp_kernel(const float* __restrict__ A, const float* __restrict__ W,
                const float* __restrict__ b, float* __restrict__ C, int do_relu)
{
    __shared__ float sA[256];
    const int row = blockIdx.x;
    const int tid = threadIdx.x;
    sA[tid] = A[row * 256 + tid];
    __syncthreads();

    float acc = 0.f;
    #pragma unroll 8
    for (int k = 0; k < 256; k++) acc += sA[k] * W[k * 256 + tid];
    float v = acc + b[tid];
    if (do_relu) v = fmaxf(v, 0.f);
    C[row * 256 + tid] = v;
}

__global__ void head_kernel(const float* __restrict__ Wc3,
                            const float* __restrict__ bc3)
{
    const int w    = threadIdx.x >> 5;
    const int lane = threadIdx.x & 31;
    const int row  = blockIdx.x * 8 + w;
    float a = 0.f;
    #pragma unroll
    for (int k = lane; k < 256; k += 32) a += g_bufA[row * 256 + k] * Wc3[k];
    #pragma unroll
    for (int off = 16; off; off >>= 1) a += __shfl_xor_sync(0xffffffffu, a, off);
    if (lane == 0) g_s[row] = tanhf(a + bc3[0]);
}

__global__ void out_kernel(float* __restrict__ out)
{
    const int o = blockIdx.x;
    const int t = threadIdx.x;
    const int i = t >> 4, j = t & 15;
    out[o * 256 + t] = (i == j) ? 0.f : g_s[o];
}

// ---------------------------------------------------------------------------
extern "C" void kernel_launch(void* const* d_in, const int* in_sizes, int n_in,
                              void* d_out, int out_size)
{
    (void)in_sizes; (void)n_in; (void)out_size;
    const float* pcls = (const float*)d_in[0];
    const float* W1 = (const float*)d_in[1];  const float* b1 = (const float*)d_in[2];
    const float* g1 = (const float*)d_in[3];  const float* bt1 = (const float*)d_in[4];
    const float* W2 = (const float*)d_in[5];  const float* b2 = (const float*)d_in[6];
    const float* g2 = (const float*)d_in[7];  const float* bt2 = (const float*)d_in[8];
    const float* W3 = (const float*)d_in[9];  const float* b3 = (const float*)d_in[10];
    const float* g3 = (const float*)d_in[11]; const float* bt3 = (const float*)d_in[12];
    const float* We = (const float*)d_in[13]; const float* be = (const float*)d_in[14];
    const float* Wg1 = (const float*)d_in[15]; const float* bg1 = (const float*)d_in[16];
    const float* Wg2 = (const float*)d_in[17]; const float* bg2 = (const float*)d_in[18];
    const float* Wc1 = (const float*)d_in[19]; const float* bc1 = (const float*)d_in[20];
    const float* Wc2 = (const float*)d_in[21]; const float* bc2 = (const float*)d_in[22];
    const float* Wc3 = (const float*)d_in[23]; const float* bc3 = (const float*)d_in[24];

    float *p_fmean, *p_bufA, *p_bufB, *p_wc1s;
    cudaGetSymbolAddress((void**)&p_fmean, g_fmean);
    cudaGetSymbolAddress((void**)&p_bufA,  g_bufA);
    cudaGetSymbolAddress((void**)&p_bufB,  g_bufB);
    cudaGetSymbolAddress((void**)&p_wc1s,  g_wc1s);

    cudaFuncSetAttribute(pointnet_mma_kernel,
                         cudaFuncAttributeMaxDynamicSharedMemorySize, SMEM_BYTES);

    // launches 1-3: one-shot weight prep (pointnet = launch #4 for ncu)
    prep_misc_kernel<<<256, 256>>>(Wc1, W1, b1, g1, bt1, b2, g2, bt2, b3, g3, bt3);
    prep_w2_kernel<<<32, 256>>>(W2, g2);
    prep_w3_kernel<<<128, 256>>>(W3, g3);

    pointnet_mma_kernel<<<PARTS, THREADS, SMEM_BYTES>>>(pcls);

    fmean_kernel<<<NOBJ, 256>>>();
    mlp_kernel<<<NOBJ, 256>>>(p_fmean, We, be, p_bufA, 0);
    mlp_kernel<<<NOBJ, 256>>>(p_bufA, Wg1, bg1, p_bufB, 1);
    mlp_kernel<<<NOBJ, 256>>>(p_bufB, Wg2, bg2, p_bufA, 0);
    mlp_kernel<<<NOBJ, 256>>>(p_bufA, p_wc1s, bc1, p_bufB, 1);
    mlp_kernel<<<NOBJ, 256>>>(p_bufB, Wc2, bc2, p_bufA, 1);
    head_kernel<<<64, 256>>>(Wc3, bc3);
    out_kernel<<<NOBJ, 256>>>((float*)d_out);
}

// round 16
// speedup vs baseline: 4.5231x; 1.1049x over previous
#include <cuda_runtime.h>
#include <cuda_bf16.h>
#include <math.h>
#include <float.h>
#include <stdint.h>

// ---------------------------------------------------------------------------
// Connectivity3D: fused PointNet (6->64->128->256 + BN + maxpool) on tensor
// cores using 3-pass bf16-split m16n8k16 mma.sync, then the algebraically-
// collapsed GCN/edge-MLP head (constant per object).
// R16 (tcgen05 is unavailable: harness ptxas targets sm_103, not sm_103a):
//  - stage-1 SIMT + pts LDG hidden in the MMA pipe-drain shadows
//  - barriers 4 -> 2 per tile
//  - ldmatrix.x4 for all A fragments (16 LDS -> 4 LDSM per kt)
//  - dead sW2 smem copy removed (smem 227 -> 192 KB)
// Arithmetic identical to R14: rel_err must stay 3.409998e-06 exactly.
// ---------------------------------------------------------------------------

#define PARTS 8192
#define PPTS  512
#define NOBJ  512
#define TP    64
#define NIT   (PPTS / TP)   // 8
#define THREADS 512

#define LDW2W 136   // prefolded W2 packed words (register-cached fragments)
#define LDW3W 264   // 64 kp x 264  (264 % 32 == 8 -> B frags conflict-free)
#define LDH1W 36    // 64 rows x 36 ( 36 % 32 == 4 -> A frags conflict-free)
#define LDH2W 68    // 64 rows x 68 ( 68 % 32 == 4)

// scratch (device globals: no allocations allowed)
__device__ float    g_feat[PARTS * 256];
__device__ float    g_fmean[NOBJ * 256];
__device__ float    g_bufA[NOBJ * 256];
__device__ float    g_bufB[NOBJ * 256];
__device__ float    g_wc1s[256 * 256];
__device__ float    g_s[NOBJ];
__device__ unsigned g_w2h[32 * LDW2W];
__device__ unsigned g_w2l[32 * LDW2W];
__device__ unsigned g_w3h[64 * LDW3W];
__device__ unsigned g_w3l[64 * LDW3W];
__device__ float    g_w1f[6 * 64];
__device__ float    g_b1f[64];
__device__ float    g_b2f[128];
__device__ float    g_b3f[256];

// ---- shared layout (32-bit words) ----
#define OFF_W3H 0
#define OFF_W3L (OFF_W3H + 64 * LDW3W)      // 16896
#define OFF_H1H (OFF_W3L + 64 * LDW3W)      // 33792
#define OFF_H1L (OFF_H1H + 64 * LDH1W)      // 36096
#define OFF_H2H (OFF_H1L + 64 * LDH1W)      // 38400
#define OFF_H2L (OFF_H2H + 64 * LDH2W)      // 42752
#define OFF_PTS (OFF_H2L + 64 * LDH2W)      // 47104
#define OFF_RED (OFF_PTS + TP * 6)          // 47488
#define SMEM_WORDS (OFF_RED + 512)          // 48000
#define SMEM_BYTES (SMEM_WORDS * 4)         // 192000 B

__device__ __forceinline__ void bfsplit1(float x, __nv_bfloat16& h, __nv_bfloat16& l) {
    h = __float2bfloat16_rn(x);
    l = __float2bfloat16_rn(x - __bfloat162float(h));
}
__device__ __forceinline__ void pack2(float x0, float x1, unsigned& hi, unsigned& lo) {
    __nv_bfloat16 h0, l0, h1, l1;
    bfsplit1(x0, h0, l0);
    bfsplit1(x1, h1, l1);
    __nv_bfloat162 hp = __halves2bfloat162(h0, h1);   // .x = low 16b = even k
    __nv_bfloat162 lp = __halves2bfloat162(l0, l1);
    hi = *reinterpret_cast<unsigned*>(&hp);
    lo = *reinterpret_cast<unsigned*>(&lp);
}
__device__ __forceinline__ void mma16(float c[4], const unsigned a[4], const unsigned b[2]) {
    asm volatile("mma.sync.aligned.m16n8k16.row.col.f32.bf16.bf16.f32 "
                 "{%0,%1,%2,%3}, {%4,%5,%6,%7}, {%8,%9}, {%0,%1,%2,%3};"
                 : "+f"(c[0]), "+f"(c[1]), "+f"(c[2]), "+f"(c[3])
                 : "r"(a[0]), "r"(a[1]), "r"(a[2]), "r"(a[3]), "r"(b[0]), "r"(b[1]));
}
__device__ __forceinline__ void mma3(float c[4],
                                     const unsigned ah[4], const unsigned al[4],
                                     const unsigned bh[2], const unsigned bl[2]) {
    mma16(c, ah, bh);
    mma16(c, ah, bl);
    mma16(c, al, bh);
}
__device__ __forceinline__ uint32_t smem_u32(const void* p) {
    uint32_t a;
    asm("{ .reg .u64 t; cvta.to.shared.u64 t, %1; cvt.u32.u64 %0, t; }" : "=r"(a) : "l"(p));
    return a;
}
// ldmatrix x4: m0..m3 = (rows r..r+7, k-lo) (r+8.., k-lo) (r.., k-hi) (r+8.., k-hi)
__device__ __forceinline__ void ldsm_x4(unsigned r[4], uint32_t addr) {
    asm volatile("ldmatrix.sync.aligned.m8n8.x4.shared.b16 {%0,%1,%2,%3}, [%4];"
                 : "=r"(r[0]), "=r"(r[1]), "=r"(r[2]), "=r"(r[3]) : "r"(addr));
}

// ---------------------------------------------------------------------------
// Prep kernels (launches 1-3; pointnet is launch #4 for ncu)
// ---------------------------------------------------------------------------
__global__ void prep_misc_kernel(const float* __restrict__ Wc1,
                                 const float* __restrict__ W1, const float* __restrict__ b1,
                                 const float* __restrict__ g1, const float* __restrict__ bt1,
                                 const float* __restrict__ b2, const float* __restrict__ g2,
                                 const float* __restrict__ bt2,
                                 const float* __restrict__ b3, const float* __restrict__ g3,
                                 const float* __restrict__ bt3)
{
    const int i = blockIdx.x * 256 + threadIdx.x;
    g_wc1s[i] = Wc1[i] + Wc1[256 * 256 + i];
    if (blockIdx.x == 0) {
        const int t = threadIdx.x;
        g_w1f[t] = W1[t] * g1[t & 63];
        if (t < 128) g_w1f[t + 256] = W1[t + 256] * g1[t & 63];
        if (t < 64)  g_b1f[t] = b1[t] * g1[t] + bt1[t];
        if (t < 128) g_b2f[t] = b2[t] * g2[t] + bt2[t];
        g_b3f[t] = b3[t] * g3[t] + bt3[t];
    }
}

__global__ void prep_w2_kernel(const float* __restrict__ W2, const float* __restrict__ g2)
{
    const int i = blockIdx.x * 256 + threadIdx.x;   // 8192
    const int k = i >> 7, c = i & 127;
    float v = W2[i] * __ldg(&g2[c]);
    __nv_bfloat16 h, l;
    bfsplit1(v, h, l);
    const int bi = ((k >> 1) * LDW2W + c) * 2 + (k & 1);
    reinterpret_cast<__nv_bfloat16*>(g_w2h)[bi] = h;
    reinterpret_cast<__nv_bfloat16*>(g_w2l)[bi] = l;
}

__global__ void prep_w3_kernel(const float* __restrict__ W3, const float* __restrict__ g3)
{
    const int i = blockIdx.x * 256 + threadIdx.x;   // 32768
    const int k = i >> 8, c = i & 255;
    float v = W3[i] * __ldg(&g3[c]);
    __nv_bfloat16 h, l;
    bfsplit1(v, h, l);
    const int bi = ((k >> 1) * LDW3W + c) * 2 + (k & 1);
    reinterpret_cast<__nv_bfloat16*>(g_w3h)[bi] = h;
    reinterpret_cast<__nv_bfloat16*>(g_w3l)[bi] = l;
}

// ---------------------------------------------------------------------------
// Kernel A: one block (512 thr = 16 warps) per part; 64-point tiles,
// software-pipelined: pts(t+1) hides under stage-2 drain, stage-1(t+1)
// hides under stage-3 drain. 2 barriers per tile.
// ---------------------------------------------------------------------------
__global__ __launch_bounds__(THREADS, 1)
void pointnet_mma_kernel(const float* __restrict__ pcls)
{
    extern __shared__ unsigned smw[];
    unsigned* sW3h = smw + OFF_W3H;
    unsigned* sW3l = smw + OFF_W3L;
    unsigned* sH1h = smw + OFF_H1H;
    unsigned* sH1l = smw + OFF_H1L;
    unsigned* sH2h = smw + OFF_H2H;
    unsigned* sH2l = smw + OFF_H2L;
    float* sPt  = reinterpret_cast<float*>(smw + OFF_PTS);
    float* sRed = reinterpret_cast<float*>(smw + OFF_RED);
    __nv_bfloat16* sH1h_b = reinterpret_cast<__nv_bfloat16*>(sH1h);
    __nv_bfloat16* sH1l_b = reinterpret_cast<__nv_bfloat16*>(sH1l);

    const int tid  = threadIdx.x;
    const int w    = tid >> 5;        // 0..15
    const int lane = tid & 31;
    const int g    = lane >> 2;       // 0..7
    const int tg   = lane & 3;        // 0..3
    const int part = blockIdx.x;

    // ---- prologue: copy prefolded W3 (hi+lo) into smem, uint4 ----
    {
        const uint4* s3h = reinterpret_cast<const uint4*>(g_w3h);
        const uint4* s3l = reinterpret_cast<const uint4*>(g_w3l);
        uint4* d3h = reinterpret_cast<uint4*>(sW3h);
        uint4* d3l = reinterpret_cast<uint4*>(sW3l);
        #pragma unroll 4
        for (int i = tid; i < (64 * LDW3W) / 4; i += THREADS) {
            d3h[i] = s3h[i];
            d3l[i] = s3l[i];
        }
    }

    // ---- per-thread constants ----
    const int c1 = tid & 63;
    const int pg = tid >> 6;          // 0..7 -> 8 points each
    float w1r[6];
    #pragma unroll
    for (int d = 0; d < 6; d++) w1r[d] = __ldg(&g_w1f[d * 64 + c1]);
    const float b1f = __ldg(&g_b1f[c1]);

    const int mp2 = (w & 1) * 32;     // stage-2 rows (2 m-tiles of 16)
    const int nb2 = (w >> 1) * 16;    // stage-2 cols (2 n-tiles of 8)
    const int mh3 = (w & 1) * 32;     // stage-3 rows
    const int mhalf = w & 1;
    const int nb3 = (w >> 1) * 32;    // stage-3 cols (4 n-tiles of 8)

    // ldmatrix lane-address bases (constant across tiles; +32 B per kt)
    const int lrow = lane & 15;
    const int lkof = (lane & 16) ? 4 : 0;
    uint32_t a2b[2][2], a3b[2][2];    // [mt][hi/lo]
    {
        const uint32_t h1h = smem_u32(sH1h), h1l = smem_u32(sH1l);
        const uint32_t h2h = smem_u32(sH2h), h2l = smem_u32(sH2l);
        #pragma unroll
        for (int mt = 0; mt < 2; mt++) {
            const uint32_t o1 = 4u * ((mp2 + mt * 16 + lrow) * LDH1W + lkof);
            const uint32_t o2 = 4u * ((mh3 + mt * 16 + lrow) * LDH2W + lkof);
            a2b[mt][0] = h1h + o1; a2b[mt][1] = h1l + o1;
            a3b[mt][0] = h2h + o2; a3b[mt][1] = h2l + o2;
        }
    }

    // stage-2 B fragments: register-cached once from prefolded gmem
    unsigned b2r[4][2][2][2];         // [kt][nt][hi/lo][reg]
    #pragma unroll
    for (int kt = 0; kt < 4; kt++)
        #pragma unroll
        for (int nt = 0; nt < 2; nt++) {
            const int o = (kt * 8 + tg) * LDW2W + nb2 + nt * 8 + g;
            b2r[kt][nt][0][0] = __ldg(&g_w2h[o]);
            b2r[kt][nt][0][1] = __ldg(&g_w2h[o + 4 * LDW2W]);
            b2r[kt][nt][1][0] = __ldg(&g_w2l[o]);
            b2r[kt][nt][1][1] = __ldg(&g_w2l[o + 4 * LDW2W]);
        }
    float bb[2][2];
    #pragma unroll
    for (int nt = 0; nt < 2; nt++) {
        const int n = nb2 + nt * 8 + 2 * tg;
        bb[nt][0] = __ldg(&g_b2f[n]);
        bb[nt][1] = __ldg(&g_b2f[n + 1]);
    }

    float run_e[4], run_o[4];
    #pragma unroll
    for (int nt = 0; nt < 4; nt++) { run_e[nt] = -FLT_MAX; run_o[nt] = -FLT_MAX; }

    const float* pbase = pcls + (size_t)part * (PPTS * 6);

    // ---- prologue of pipeline: pts(0) + stage1(0) ----
    if (tid < TP * 6) sPt[tid] = pbase[tid];
    __syncthreads();
    #pragma unroll
    for (int r = 0; r < 8; r++) {
        const int p = pg * 8 + r;
        const float* pt = &sPt[p * 6];
        float a = b1f + pt[0]*w1r[0] + pt[1]*w1r[1] + pt[2]*w1r[2]
                      + pt[3]*w1r[3] + pt[4]*w1r[4] + pt[5]*w1r[5];
        a = fmaxf(a, 0.f);
        __nv_bfloat16 h, l;
        bfsplit1(a, h, l);
        const int bi = p * (LDH1W * 2) + c1;
        sH1h_b[bi] = h;
        sH1l_b[bi] = l;
    }
    __syncthreads();

    for (int t = 0; t < NIT; t++) {
        // ======== stage 2 (bf16x3 mma.sync): 64 x 128 ========
        float c2[2][2][4];
        #pragma unroll
        for (int mt = 0; mt < 2; mt++)
            #pragma unroll
            for (int nt = 0; nt < 2; nt++)
                #pragma unroll
                for (int j = 0; j < 4; j++) c2[mt][nt][j] = 0.f;

        #pragma unroll
        for (int kt = 0; kt < 4; kt++) {
            unsigned ah[2][4], al[2][4];
            ldsm_x4(ah[0], a2b[0][0] + kt * 32);
            ldsm_x4(al[0], a2b[0][1] + kt * 32);
            ldsm_x4(ah[1], a2b[1][0] + kt * 32);
            ldsm_x4(al[1], a2b[1][1] + kt * 32);
            #pragma unroll
            for (int nt = 0; nt < 2; nt++) {
                mma3(c2[0][nt], ah[0], al[0], b2r[kt][nt][0], b2r[kt][nt][1]);
                mma3(c2[1][nt], ah[1], al[1], b2r[kt][nt][0], b2r[kt][nt][1]);
            }
        }

        // ---- shadow: pts(t+1) global load (hides stage-2 pipe drain) ----
        float ptv = 0.f;
        const bool havep = (t + 1 < NIT) && (tid < TP * 6);
        if (havep) ptv = pbase[(t + 1) * TP * 6 + tid];

        // ---- stage-2 epilogue: bias+relu, split, store H2 ----
        #pragma unroll
        for (int mt = 0; mt < 2; mt++)
            #pragma unroll
            for (int nt = 0; nt < 2; nt++) {
                float v0 = fmaxf(c2[mt][nt][0] + bb[nt][0], 0.f);
                float v1 = fmaxf(c2[mt][nt][1] + bb[nt][1], 0.f);
                float v2 = fmaxf(c2[mt][nt][2] + bb[nt][0], 0.f);
                float v3 = fmaxf(c2[mt][nt][3] + bb[nt][1], 0.f);
                unsigned h0, l0, h1, l1;
                pack2(v0, v1, h0, l0);
                pack2(v2, v3, h1, l1);
                const int wcol = (nb2 >> 1) + nt * 4 + tg;
                const int r0 = mp2 + mt * 16 + g;
                sH2h[r0 * LDH2W + wcol]       = h0;
                sH2l[r0 * LDH2W + wcol]       = l0;
                sH2h[(r0 + 8) * LDH2W + wcol] = h1;
                sH2l[(r0 + 8) * LDH2W + wcol] = l1;
            }
        if (havep) sPt[tid] = ptv;
        __syncthreads();

        // ======== stage 3 (bf16x3 mma.sync): 64 x 256 ========
        float d[2][4][4];
        #pragma unroll
        for (int mt = 0; mt < 2; mt++)
            #pragma unroll
            for (int nt = 0; nt < 4; nt++)
                #pragma unroll
                for (int j = 0; j < 4; j++) d[mt][nt][j] = 0.f;

        #pragma unroll
        for (int kt = 0; kt < 8; kt++) {
            unsigned ah[2][4], al[2][4];
            ldsm_x4(ah[0], a3b[0][0] + kt * 32);
            ldsm_x4(al[0], a3b[0][1] + kt * 32);
            ldsm_x4(ah[1], a3b[1][0] + kt * 32);
            ldsm_x4(al[1], a3b[1][1] + kt * 32);
            #pragma unroll
            for (int nt = 0; nt < 4; nt++) {
                unsigned bh[2], bl[2];
                const unsigned* qh = &sW3h[(kt * 8 + tg) * LDW3W + nb3 + nt * 8 + g];
                const unsigned* ql = &sW3l[(kt * 8 + tg) * LDW3W + nb3 + nt * 8 + g];
                bh[0] = qh[0]; bh[1] = qh[4 * LDW3W];
                bl[0] = ql[0]; bl[1] = ql[4 * LDW3W];
                mma3(d[0][nt], ah[0], al[0], bh, bl);
                mma3(d[1][nt], ah[1], al[1], bh, bl);
            }
        }

        // ---- shadow: stage-1(t+1) (hides stage-3 pipe drain) ----
        if (t + 1 < NIT) {
            #pragma unroll
            for (int r = 0; r < 8; r++) {
                const int p = pg * 8 + r;
                const float* pt = &sPt[p * 6];
                float a = b1f + pt[0]*w1r[0] + pt[1]*w1r[1] + pt[2]*w1r[2]
                              + pt[3]*w1r[3] + pt[4]*w1r[4] + pt[5]*w1r[5];
                a = fmaxf(a, 0.f);
                __nv_bfloat16 h, l;
                bfsplit1(a, h, l);
                const int bi = p * (LDH1W * 2) + c1;
                sH1h_b[bi] = h;
                sH1l_b[bi] = l;
            }
        }

        // ---- stage-3 accumulator reads: running max ----
        #pragma unroll
        for (int nt = 0; nt < 4; nt++) {
            run_e[nt] = fmaxf(run_e[nt],
                        fmaxf(fmaxf(d[0][nt][0], d[0][nt][2]),
                              fmaxf(d[1][nt][0], d[1][nt][2])));
            run_o[nt] = fmaxf(run_o[nt],
                        fmaxf(fmaxf(d[0][nt][1], d[0][nt][3]),
                              fmaxf(d[1][nt][1], d[1][nt][3])));
        }
        __syncthreads();
    }

    // ---- warp-level max over point rows -> sRed; combine the 2 m-halves ----
    #pragma unroll
    for (int nt = 0; nt < 4; nt++) {
        float e = run_e[nt], o = run_o[nt];
        #pragma unroll
        for (int off = 4; off <= 16; off <<= 1) {
            e = fmaxf(e, __shfl_xor_sync(0xffffffffu, e, off));
            o = fmaxf(o, __shfl_xor_sync(0xffffffffu, o, off));
        }
        if (g == 0) {
            const int ce = nb3 + nt * 8 + 2 * tg;
            sRed[mhalf * 256 + ce]     = e;
            sRed[mhalf * 256 + ce + 1] = o;
        }
    }
    __syncthreads();
    if (tid < 256) {
        const float v = fmaxf(sRed[tid], sRed[256 + tid]) + __ldg(&g_b3f[tid]);
        g_feat[part * 256 + tid] = v;
    }
}

// ---------------------------------------------------------------------------
__global__ void fmean_kernel()
{
    const int o = blockIdx.x;
    const int c = threadIdx.x;
    float s = 0.f;
    #pragma unroll
    for (int k = 0; k < 16; k++) s += g_feat[(o * 16 + k) * 256 + c];
    g_fmean[o * 256 + c] = s * (1.f / 16.f);
}

__global__ __launch_bounds__(256)
void mlp_kernel(const float* __restrict__ A, const float* __restrict__ W,
                const float* __restrict__ b, float* __restrict__ C, int do_relu)
{
    __shared__ float sA[256];
    const int row = blockIdx.x;
    const int tid = threadIdx.x;
    sA[tid] = A[row * 256 + tid];
    __syncthreads();

    float acc = 0.f;
    #pragma unroll 8
    for (int k = 0; k < 256; k++) acc += sA[k] * W[k * 256 + tid];
    float v = acc + b[tid];
    if (do_relu) v = fmaxf(v, 0.f);
    C[row * 256 + tid] = v;
}

__global__ void head_kernel(const float* __restrict__ Wc3,
                            const float* __restrict__ bc3)
{
    const int w    = threadIdx.x >> 5;
    const int lane = threadIdx.x & 31;
    const int row  = blockIdx.x * 8 + w;
    float a = 0.f;
    #pragma unroll
    for (int k = lane; k < 256; k += 32) a += g_bufA[row * 256 + k] * Wc3[k];
    #pragma unroll
    for (int off = 16; off; off >>= 1) a += __shfl_xor_sync(0xffffffffu, a, off);
    if (lane == 0) g_s[row] = tanhf(a + bc3[0]);
}

__global__ void out_kernel(float* __restrict__ out)
{
    const int o = blockIdx.x;
    const int t = threadIdx.x;
    const int i = t >> 4, j = t & 15;
    out[o * 256 + t] = (i == j) ? 0.f : g_s[o];
}

// ---------------------------------------------------------------------------
extern "C" void kernel_launch(void* const* d_in, const int* in_sizes, int n_in,
                              void* d_out, int out_size)
{
    (void)in_sizes; (void)n_in; (void)out_size;
    const float* pcls = (const float*)d_in[0];
    const float* W1 = (const float*)d_in[1];  const float* b1 = (const float*)d_in[2];
    const float* g1 = (const float*)d_in[3];  const float* bt1 = (const float*)d_in[4];
    const float* W2 = (const float*)d_in[5];  const float* b2 = (const float*)d_in[6];
    const float* g2 = (const float*)d_in[7];  const float* bt2 = (const float*)d_in[8];
    const float* W3 = (const float*)d_in[9];  const float* b3 = (const float*)d_in[10];
    const float* g3 = (const float*)d_in[11]; const float* bt3 = (const float*)d_in[12];
    const float* We = (const float*)d_in[13]; const float* be = (const float*)d_in[14];
    const float* Wg1 = (const float*)d_in[15]; const float* bg1 = (const float*)d_in[16];
    const float* Wg2 = (const float*)d_in[17]; const float* bg2 = (const float*)d_in[18];
    const float* Wc1 = (const float*)d_in[19]; const float* bc1 = (const float*)d_in[20];
    const float* Wc2 = (const float*)d_in[21]; const float* bc2 = (const float*)d_in[22];
    const float* Wc3 = (const float*)d_in[23]; const float* bc3 = (const float*)d_in[24];

    float *p_fmean, *p_bufA, *p_bufB, *p_wc1s;
    cudaGetSymbolAddress((void**)&p_fmean, g_fmean);
    cudaGetSymbolAddress((void**)&p_bufA,  g_bufA);
    cudaGetSymbolAddress((void**)&p_bufB,  g_bufB);
    cudaGetSymbolAddress((void**)&p_wc1s,  g_wc1s);

    cudaFuncSetAttribute(pointnet_mma_kernel,
                         cudaFuncAttributeMaxDynamicSharedMemorySize, SMEM_BYTES);

    // launches 1-3: one-shot weight prep (pointnet = launch #4 for ncu)
    prep_misc_kernel<<<256, 256>>>(Wc1, W1, b1, g1, bt1, b2, g2, bt2, b3, g3, bt3);
    prep_w2_kernel<<<32, 256>>>(W2, g2);
    prep_w3_kernel<<<128, 256>>>(W3, g3);

    pointnet_mma_kernel<<<PARTS, THREADS, SMEM_BYTES>>>(pcls);

    fmean_kernel<<<NOBJ, 256>>>();
    mlp_kernel<<<NOBJ, 256>>>(p_fmean, We, be, p_bufA, 0);
    mlp_kernel<<<NOBJ, 256>>>(p_bufA, Wg1, bg1, p_bufB, 1);
    mlp_kernel<<<NOBJ, 256>>>(p_bufB, Wg2, bg2, p_bufA, 0);
    mlp_kernel<<<NOBJ, 256>>>(p_bufA, p_wc1s, bc1, p_bufB, 1);
    mlp_kernel<<<NOBJ, 256>>>(p_bufB, Wc2, bc2, p_bufA, 1);
    head_kernel<<<64, 256>>>(Wc3, bc3);
    out_kernel<<<NOBJ, 256>>>((float*)d_out);
}